// round 11
// baseline (speedup 1.0000x reference)
#include <cuda_runtime.h>
#include <cuda_fp16.h>
#include <math.h>
#include <stdint.h>

#define TB_B  2
#define TB_S  2048
#define TB_D  1024
#define TB_H  16
#define TB_DH 64
#define TB_FF 4096
#define TB_M  4096

// ---------------- scratch (no allocations allowed) ----------------
static __device__ float  g_x2[TB_M * TB_D];
static __device__ __half g_h16 [TB_M * TB_D];
static __device__ __half g_q16 [TB_M * TB_D];
static __device__ __half g_k16 [TB_M * TB_D];
static __device__ __half g_v16 [TB_M * TB_D];
static __device__ __half g_o16 [TB_M * TB_D];
static __device__ __half g_h216[TB_M * TB_D];
static __device__ __half g_mid16[(size_t)TB_M * TB_FF];
static __device__ __half g_wq16[TB_D * TB_D];
static __device__ __half g_wk16[TB_D * TB_D];
static __device__ __half g_wv16[TB_D * TB_D];
static __device__ __half g_wo16[TB_D * TB_D];
static __device__ __half g_w116[TB_FF * TB_D];
static __device__ __half g_w216[TB_D * TB_FF];

// ---------------- helpers ----------------
static __device__ __forceinline__ uint32_t smem_u32(const void* p) {
    uint32_t a;
    asm("{ .reg .u64 t; cvta.to.shared.u64 t, %1; cvt.u32.u64 %0, t; }" : "=r"(a) : "l"(p));
    return a;
}
static __device__ __forceinline__ void cp16(uint32_t d, const void* s) {
    asm volatile("cp.async.cg.shared.global [%0], [%1], 16;" :: "r"(d), "l"(s) : "memory");
}
#define CP_COMMIT()  asm volatile("cp.async.commit_group;" ::: "memory")
#define CP_WAIT(n)   asm volatile("cp.async.wait_group %0;" :: "n"(n) : "memory")

#define LDSM4(r0, r1, r2, r3, addr) \
    asm volatile("ldmatrix.sync.aligned.m8n8.x4.shared.b16 {%0,%1,%2,%3}, [%4];" \
                 : "=r"(r0), "=r"(r1), "=r"(r2), "=r"(r3) : "r"(addr))

#define LDSM4T(r0, r1, r2, r3, addr) \
    asm volatile("ldmatrix.sync.aligned.m8n8.x4.trans.shared.b16 {%0,%1,%2,%3}, [%4];" \
                 : "=r"(r0), "=r"(r1), "=r"(r2), "=r"(r3) : "r"(addr))

#define MMAF16(d, a, b0v, b1v) \
    asm volatile("mma.sync.aligned.m16n8k16.row.col.f32.f16.f16.f32 " \
                 "{%0,%1,%2,%3}, {%4,%5,%6,%7}, {%8,%9}, {%0,%1,%2,%3};" \
                 : "+f"((d)[0]), "+f"((d)[1]), "+f"((d)[2]), "+f"((d)[3]) \
                 : "r"((a)[0]), "r"((a)[1]), "r"((a)[2]), "r"((a)[3]), \
                   "r"(b0v), "r"(b1v))

static __device__ __forceinline__ float gelu_f(float x) {
    return 0.5f * x * (1.0f + erff(x * 0.70710678118654752440f));
}
static __device__ __forceinline__ uint32_t pack_h2(float a, float b) {
    __half2 h = __floats2half2_rn(a, b);
    return *(uint32_t*)&h;
}

// ---------------- weight convert kernels (fp32 -> fp16) ----------------
static __device__ __forceinline__ void conv_one(
    const float* __restrict__ s, __half* __restrict__ d, size_t i)
{
    const float4 v = ((const float4*)s)[i];
    ((__half2*)d)[i * 2]     = __floats2half2_rn(v.x, v.y);
    ((__half2*)d)[i * 2 + 1] = __floats2half2_rn(v.z, v.w);
}

__global__ void __launch_bounds__(256) conv4_kernel(
    const float* wq, __half* wq16, const float* wk, __half* wk16,
    const float* wv, __half* wv16, const float* wo, __half* wo16)
{
    const int which = blockIdx.x >> 10;
    const size_t i  = (size_t)(blockIdx.x & 1023) * 256 + threadIdx.x;
    if (which == 0)      conv_one(wq, wq16, i);
    else if (which == 1) conv_one(wk, wk16, i);
    else if (which == 2) conv_one(wv, wv16, i);
    else                 conv_one(wo, wo16, i);
}

__global__ void __launch_bounds__(256) convFF_kernel(
    const float* w1, __half* w116, const float* w2, __half* w216)
{
    const int which = blockIdx.x >> 12;
    const size_t i  = (size_t)(blockIdx.x & 4095) * 256 + threadIdx.x;
    if (which == 0) conv_one(w1, w116, i);
    else            conv_one(w2, w216, i);
}

// ---------------- rmsnorm -> fp16 ----------------
__global__ void __launch_bounds__(256) rmsnorm_h_kernel(
    const float* __restrict__ x, const float* __restrict__ g, __half* __restrict__ oh)
{
    const int row = blockIdx.x;
    const int tid = threadIdx.x;
    const float4 xv = ((const float4*)(x + (size_t)row * TB_D))[tid];
    float ss = xv.x * xv.x + xv.y * xv.y + xv.z * xv.z + xv.w * xv.w;
    #pragma unroll
    for (int off = 16; off; off >>= 1)
        ss += __shfl_xor_sync(0xffffffffu, ss, off);
    __shared__ float ws[8];
    __shared__ float s_scale;
    const int wid = tid >> 5, lane = tid & 31;
    if (lane == 0) ws[wid] = ss;
    __syncthreads();
    if (tid == 0) {
        float t = 0.f;
        #pragma unroll
        for (int i = 0; i < 8; i++) t += ws[i];
        s_scale = rsqrtf(t * (1.0f / (float)TB_D) + 1e-5f);
    }
    __syncthreads();
    const float sc = s_scale;
    const float4 gv = ((const float4*)g)[tid];
    const size_t o = (size_t)row * TB_D + tid * 4;
    *(__half2*)(oh + o)     = __floats2half2_rn(xv.x * gv.x * sc, xv.y * gv.y * sc);
    *(__half2*)(oh + o + 2) = __floats2half2_rn(xv.z * gv.z * sc, xv.w * gv.w * sc);
}

// ---------------- fp16 GEMM, 128x128 tile, 256 threads ----------------
// 8 warps (2x4), warp tile 64x32, 3-stage cp.async pipeline,
// double-buffered register fragments across ks (LDSM ks+1 issued before MMA ks).
#define ARR_BYTES   (128 * 144)
#define STAGE_BYTES (2 * ARR_BYTES)             // 36864 (A + B)
#define N_STAGES    3
#define GEMM_SMEM   (N_STAGES * STAGE_BYTES)    // 110592

template<int EPI>   // 1=gelu->fp16, 2=+res fp32, 3=fp16 scaled
static __device__ __forceinline__ void tc_gemm_core(
    const __half* __restrict__ A, const __half* __restrict__ B,
    const float* __restrict__ res, float* __restrict__ Cf,
    __half* __restrict__ Ch, float oscale,
    int N, int K)
{
    extern __shared__ char smc[];
    const uint32_t sb  = smem_u32(smc);
    const int tid  = threadIdx.x;
    const int lane = tid & 31;
    const int wm   = (tid >> 5) >> 2;     // 0..1
    const int wn   = (tid >> 5) & 3;      // 0..3
    const int bm   = blockIdx.y * 128;
    const int bn   = blockIdx.x * 128;
    const int nch  = K >> 6;

    auto load_chunk = [&](int kc, int st) {
        const uint32_t db  = sb + (uint32_t)st * STAGE_BYTES;
        const int kof = kc * 64;
        #pragma unroll
        for (int it = 0; it < 4; ++it) {
            const int g  = tid + it * 256;
            const int r  = g >> 3, gc = g & 7;
            const uint32_t off = (uint32_t)(r * 144 + gc * 16);
            cp16(db + off,             A + (size_t)(bm + r) * K + kof + gc * 8);
            cp16(db + ARR_BYTES + off, B + (size_t)(bn + r) * K + kof + gc * 8);
        }
        CP_COMMIT();
    };

    float acc[4][4][4];
    #pragma unroll
    for (int mi = 0; mi < 4; mi++)
        #pragma unroll
        for (int ni = 0; ni < 4; ni++)
            #pragma unroll
            for (int r = 0; r < 4; r++) acc[mi][ni][r] = 0.f;

    load_chunk(0, 0);
    if (nch > 1) load_chunk(1, 1);
    if (nch > 2) load_chunk(2, 2);

    const uint32_t aRow = (uint32_t)(wm * 64 + (lane & 15));
    const uint32_t aCol = (uint32_t)((lane >> 4) * 8);
    const int grp = lane >> 3, r8 = lane & 7;
    const uint32_t bRow = (uint32_t)(wn * 32 + (grp >> 1) * 8 + r8);
    const uint32_t bCol = (uint32_t)((grp & 1) * 8);

    uint32_t a[2][4][4], b[2][4][2];   // double-buffered fragments

    for (int i = 0; i < nch; ++i) {
        const int p = i % N_STAGES;
        if (i + 2 < nch)      CP_WAIT(2);
        else if (i + 1 < nch) CP_WAIT(1);
        else                  CP_WAIT(0);
        __syncthreads();

        const uint32_t dA = sb + (uint32_t)p * STAGE_BYTES;
        const uint32_t dB = dA + ARR_BYTES;

        // prefetch fragments for ks=0
        {
            #pragma unroll
            for (int mi = 0; mi < 4; mi++) {
                const uint32_t ao = (aRow + mi * 16) * 144 + aCol * 2;
                LDSM4(a[0][mi][0], a[0][mi][1], a[0][mi][2], a[0][mi][3], dA + ao);
            }
            #pragma unroll
            for (int nj = 0; nj < 2; nj++) {
                const uint32_t bo = (bRow + nj * 16) * 144 + bCol * 2;
                LDSM4(b[0][nj*2][0], b[0][nj*2][1], b[0][nj*2+1][0], b[0][nj*2+1][1], dB + bo);
            }
        }

        #pragma unroll
        for (int ks = 0; ks < 4; ++ks) {
            const int cur = ks & 1, nxt = cur ^ 1;
            if (ks < 3) {   // issue LDSM for ks+1 BEFORE MMAs of ks (independent regs)
                const uint32_t kc2 = (uint32_t)((ks + 1) * 16) * 2;
                #pragma unroll
                for (int mi = 0; mi < 4; mi++) {
                    const uint32_t ao = (aRow + mi * 16) * 144 + kc2 + aCol * 2;
                    LDSM4(a[nxt][mi][0], a[nxt][mi][1], a[nxt][mi][2], a[nxt][mi][3], dA + ao);
                }
                #pragma unroll
                for (int nj = 0; nj < 2; nj++) {
                    const uint32_t bo = (bRow + nj * 16) * 144 + kc2 + bCol * 2;
                    LDSM4(b[nxt][nj*2][0], b[nxt][nj*2][1], b[nxt][nj*2+1][0], b[nxt][nj*2+1][1], dB + bo);
                }
            }
            #pragma unroll
            for (int mi = 0; mi < 4; mi++)
                #pragma unroll
                for (int ni = 0; ni < 4; ni++)
                    MMAF16(acc[mi][ni], a[cur][mi], b[cur][ni][0], b[cur][ni][1]);
        }
        __syncthreads();
        if (i + N_STAGES < nch) load_chunk(i + N_STAGES, p);
    }

    const int rq = lane >> 2, cq = (lane & 3) * 2;
    #pragma unroll
    for (int mi = 0; mi < 4; mi++) {
        #pragma unroll
        for (int ni = 0; ni < 4; ni++) {
            const int row0 = bm + wm * 64 + mi * 16 + rq;
            const int col  = bn + wn * 32 + ni * 8 + cq;
            #pragma unroll
            for (int half = 0; half < 2; half++) {
                const int row = row0 + half * 8;
                const size_t go = (size_t)row * N + col;
                const float v0 = acc[mi][ni][half * 2 + 0];
                const float v1 = acc[mi][ni][half * 2 + 1];
                if (EPI == 2) {
                    const float2 rv = *(const float2*)(res + go);
                    float2 v; v.x = v0 + rv.x; v.y = v1 + rv.y;
                    *(float2*)(Cf + go) = v;
                } else if (EPI == 3) {
                    *(__half2*)(Ch + go) = __floats2half2_rn(v0 * oscale, v1 * oscale);
                } else {
                    *(__half2*)(Ch + go) = __floats2half2_rn(gelu_f(v0), gelu_f(v1));
                }
            }
        }
    }
}

__global__ void __launch_bounds__(256, 1) gemm_qkv_k(
    const __half* A,
    const __half* wq, const __half* wk, const __half* wv,
    __half* q, __half* k, __half* v)
{
    const __half* B; __half* C; float sc;
    if (blockIdx.z == 0)      { B = wq; C = q; sc = 0.125f; }
    else if (blockIdx.z == 1) { B = wk; C = k; sc = 1.0f; }
    else                      { B = wv; C = v; sc = 1.0f; }
    tc_gemm_core<3>(A, B, nullptr, nullptr, C, sc, TB_D, TB_D);
}
__global__ void __launch_bounds__(256, 1) gemm_res_k(
    const __half* A, const __half* B,
    const float* res, float* C, int N, int K)
{
    tc_gemm_core<2>(A, B, res, C, nullptr, 1.f, N, K);
}
__global__ void __launch_bounds__(256, 1) gemm_gelu_k(
    const __half* A, const __half* B, __half* C, int N, int K)
{
    tc_gemm_core<1>(A, B, nullptr, nullptr, C, 1.f, N, K);
}

// ---------------- fp16 tensor-core causal flash attention ----------------
#define AT_LD    72
#define AT_QB    (128 * AT_LD * 2)
#define AT_KB    (64 * AT_LD * 2)
#define AT_STB   (2 * AT_KB)
#define AT_SMEM  (AT_QB + 2 * AT_STB)

__global__ void __launch_bounds__(256, 1) attn_kernel(
    const __half* __restrict__ Qg, const __half* __restrict__ Kg,
    const __half* __restrict__ Vg, __half* __restrict__ Og)
{
    extern __shared__ char smc[];
    const uint32_t sb = smem_u32(smc);
    const uint32_t sQ = sb;

    const int qt   = gridDim.x - 1 - blockIdx.x;
    const int h    = blockIdx.y;
    const int b    = blockIdx.z;
    const int tid  = threadIdx.x;
    const int lane = tid & 31;
    const int warp = tid >> 5;

    const int qbase   = qt * 128;
    const size_t tokQ = (size_t)b * TB_S + qbase;
    const size_t tokK = (size_t)b * TB_S;
    const int hoff    = h * TB_DH;
    const int jtmax   = 2 * qt + 1;

    auto cpQ = [&]() {
        #pragma unroll
        for (int it = 0; it < 4; ++it) {
            const int g = tid + it * 256;
            const int r = g >> 3, c = g & 7;
            cp16(sQ + (uint32_t)(r * 144 + c * 16),
                 Qg + (tokQ + r) * TB_D + hoff + c * 8);
        }
        CP_COMMIT();
    };
    auto cpKV = [&](int jt, int st) {
        const uint32_t sK = sb + AT_QB + (uint32_t)st * AT_STB;
        const uint32_t sV = sK + AT_KB;
        const size_t rowb = tokK + (size_t)jt * 64;
        #pragma unroll
        for (int it = 0; it < 2; ++it) {
            const int g = tid + it * 256;
            const int r = g >> 3, c = g & 7;
            const uint32_t off = (uint32_t)(r * 144 + c * 16);
            const size_t so = (rowb + r) * TB_D + hoff + c * 8;
            cp16(sK + off, Kg + so);
            cp16(sV + off, Vg + so);
        }
        CP_COMMIT();
    };

    cpQ();
    cpKV(0, 0);
    cpKV(1, 1);

    const uint32_t aRow = (uint32_t)(warp * 16 + (lane & 15));
    const uint32_t aCol = (uint32_t)((lane >> 4) * 8);
    const int grp = lane >> 3, r8 = lane & 7;
    const uint32_t bRowB = (uint32_t)((grp >> 1) * 8 + r8);
    const uint32_t bColB = (uint32_t)((grp & 1) * 8);
    const uint32_t vRow = (uint32_t)(lane & 15);
    const uint32_t vCol = (uint32_t)((lane >> 4) * 8);

    uint32_t qa[4][4];
    float o[8][4];
    #pragma unroll
    for (int nt = 0; nt < 8; nt++)
        #pragma unroll
        for (int r = 0; r < 4; r++) o[nt][r] = 0.f;
    float m0 = -1e30f, m1 = -1e30f, l0 = 0.f, l1 = 0.f;

    const int rloc0 = lane >> 2;
    const int growA = qbase + warp * 16 + rloc0;

    for (int jt = 0; jt <= jtmax; ++jt) {
        const int st = jt & 1;
        if (jt + 1 <= jtmax) CP_WAIT(1); else CP_WAIT(0);
        __syncthreads();

        if (jt == 0) {
            #pragma unroll
            for (int ks = 0; ks < 4; ++ks) {
                const uint32_t ao = sQ + (aRow * 144 + (uint32_t)(ks * 16) * 2 + aCol * 2);
                LDSM4(qa[ks][0], qa[ks][1], qa[ks][2], qa[ks][3], ao);
            }
        }

        const uint32_t sK = sb + AT_QB + (uint32_t)st * AT_STB;
        const uint32_t sV = sK + AT_KB;

        float s[8][4];
        #pragma unroll
        for (int nt = 0; nt < 8; nt++)
            #pragma unroll
            for (int r = 0; r < 4; r++) s[nt][r] = 0.f;

        #pragma unroll
        for (int ks = 0; ks < 4; ++ks) {
            uint32_t kb[8][2];
            #pragma unroll
            for (int nt16 = 0; nt16 < 4; nt16++) {
                const uint32_t bo = sK + ((bRowB + nt16 * 16) * 144 + (uint32_t)(ks * 16) * 2 + bColB * 2);
                LDSM4(kb[nt16*2][0], kb[nt16*2][1], kb[nt16*2+1][0], kb[nt16*2+1][1], bo);
            }
            #pragma unroll
            for (int nt = 0; nt < 8; nt++)
                MMAF16(s[nt], qa[ks], kb[nt][0], kb[nt][1]);
        }

        if (jt * 64 + 63 > qbase + warp * 16) {
            const int colb = jt * 64 + 2 * (lane & 3);
            #pragma unroll
            for (int nt = 0; nt < 8; nt++) {
                const int c0 = colb + nt * 8, c1 = c0 + 1;
                if (c0 > growA)     s[nt][0] = -1e30f;
                if (c1 > growA)     s[nt][1] = -1e30f;
                if (c0 > growA + 8) s[nt][2] = -1e30f;
                if (c1 > growA + 8) s[nt][3] = -1e30f;
            }
        }

        float mx0 = -1e30f, mx1 = -1e30f;
        #pragma unroll
        for (int nt = 0; nt < 8; nt++) {
            mx0 = fmaxf(mx0, fmaxf(s[nt][0], s[nt][1]));
            mx1 = fmaxf(mx1, fmaxf(s[nt][2], s[nt][3]));
        }
        #pragma unroll
        for (int off = 1; off <= 2; off <<= 1) {
            mx0 = fmaxf(mx0, __shfl_xor_sync(0xffffffffu, mx0, off, 4));
            mx1 = fmaxf(mx1, __shfl_xor_sync(0xffffffffu, mx1, off, 4));
        }
        const float mn0 = fmaxf(m0, mx0), mn1 = fmaxf(m1, mx1);
        const float al0 = exp2f((m0 - mn0) * 1.44269504f);
        const float al1 = exp2f((m1 - mn1) * 1.44269504f);
        m0 = mn0; m1 = mn1;
        float ps0 = 0.f, ps1 = 0.f;
        #pragma unroll
        for (int nt = 0; nt < 8; nt++) {
            s[nt][0] = exp2f((s[nt][0] - mn0) * 1.44269504f);
            s[nt][1] = exp2f((s[nt][1] - mn0) * 1.44269504f);
            s[nt][2] = exp2f((s[nt][2] - mn1) * 1.44269504f);
            s[nt][3] = exp2f((s[nt][3] - mn1) * 1.44269504f);
            ps0 += s[nt][0] + s[nt][1];
            ps1 += s[nt][2] + s[nt][3];
        }
        #pragma unroll
        for (int off = 1; off <= 2; off <<= 1) {
            ps0 += __shfl_xor_sync(0xffffffffu, ps0, off, 4);
            ps1 += __shfl_xor_sync(0xffffffffu, ps1, off, 4);
        }
        l0 = l0 * al0 + ps0;
        l1 = l1 * al1 + ps1;
        #pragma unroll
        for (int nt = 0; nt < 8; nt++) {
            o[nt][0] *= al0; o[nt][1] *= al0;
            o[nt][2] *= al1; o[nt][3] *= al1;
        }

        uint32_t pa[4][4];
        #pragma unroll
        for (int j = 0; j < 4; j++) {
            pa[j][0] = pack_h2(s[2*j][0],   s[2*j][1]);
            pa[j][1] = pack_h2(s[2*j][2],   s[2*j][3]);
            pa[j][2] = pack_h2(s[2*j+1][0], s[2*j+1][1]);
            pa[j][3] = pack_h2(s[2*j+1][2], s[2*j+1][3]);
        }

        #pragma unroll
        for (int ks = 0; ks < 4; ++ks) {
            #pragma unroll
            for (int ntp = 0; ntp < 4; ntp++) {
                uint32_t v0, v1, v2, v3;
                const uint32_t vo = sV + ((vRow + ks * 16) * 144 + (vCol + ntp * 16) * 2);
                LDSM4T(v0, v1, v2, v3, vo);
                MMAF16(o[ntp*2],     pa[ks], v0, v1);
                MMAF16(o[ntp*2+1],   pa[ks], v2, v3);
            }
        }

        __syncthreads();
        if (jt + 2 <= jtmax) cpKV(jt + 2, st);
    }

    const float inv0 = 1.0f / l0, inv1 = 1.0f / l1;
    const size_t row0 = tokQ + warp * 16 + rloc0;
    const int colb = hoff + 2 * (lane & 3);
    #pragma unroll
    for (int nt = 0; nt < 8; nt++) {
        *(__half2*)(Og + row0 * TB_D + colb + nt * 8) =
            __floats2half2_rn(o[nt][0] * inv0, o[nt][1] * inv0);
        *(__half2*)(Og + (row0 + 8) * TB_D + colb + nt * 8) =
            __floats2half2_rn(o[nt][2] * inv1, o[nt][3] * inv1);
    }
}

// ---------------- launch ----------------
extern "C" void kernel_launch(void* const* d_in, const int* in_sizes, int n_in,
                              void* d_out, int out_size)
{
    const float* x  = (const float*)d_in[0];
    const float* wq = (const float*)d_in[1];
    const float* wk = (const float*)d_in[2];
    const float* wv = (const float*)d_in[3];
    const float* wo = (const float*)d_in[4];
    const float* w1 = (const float*)d_in[5];
    const float* w2 = (const float*)d_in[6];
    const float* g1 = (const float*)d_in[7];
    const float* g2 = (const float*)d_in[8];
    float* out = (float*)d_out;

    float *x2;
    __half *h16, *q16, *k16, *v16, *o16, *h216, *mid16;
    __half *wq16, *wk16, *wv16, *wo16, *w116, *w216;
    cudaGetSymbolAddress((void**)&x2,    g_x2);
    cudaGetSymbolAddress((void**)&h16,   g_h16);
    cudaGetSymbolAddress((void**)&q16,   g_q16);
    cudaGetSymbolAddress((void**)&k16,   g_k16);
    cudaGetSymbolAddress((void**)&v16,   g_v16);
    cudaGetSymbolAddress((void**)&o16,   g_o16);
    cudaGetSymbolAddress((void**)&h216,  g_h216);
    cudaGetSymbolAddress((void**)&mid16, g_mid16);
    cudaGetSymbolAddress((void**)&wq16,  g_wq16);
    cudaGetSymbolAddress((void**)&wk16,  g_wk16);
    cudaGetSymbolAddress((void**)&wv16,  g_wv16);
    cudaGetSymbolAddress((void**)&wo16,  g_wo16);
    cudaGetSymbolAddress((void**)&w116,  g_w116);
    cudaGetSymbolAddress((void**)&w216,  g_w216);

    cudaFuncSetAttribute(gemm_qkv_k,  cudaFuncAttributeMaxDynamicSharedMemorySize, GEMM_SMEM);
    cudaFuncSetAttribute(gemm_res_k,  cudaFuncAttributeMaxDynamicSharedMemorySize, GEMM_SMEM);
    cudaFuncSetAttribute(gemm_gelu_k, cudaFuncAttributeMaxDynamicSharedMemorySize, GEMM_SMEM);
    cudaFuncSetAttribute(attn_kernel, cudaFuncAttributeMaxDynamicSharedMemorySize, AT_SMEM);

    // 1: attention-weight converts
    conv4_kernel<<<4096, 256>>>(wq, wq16, wk, wk16, wv, wv16, wo, wo16);
    // 2: FFN-weight converts
    convFF_kernel<<<8192, 256>>>(w1, w116, w2, w216);
    // 3: h = rmsnorm(x, g1) -> fp16
    rmsnorm_h_kernel<<<TB_M, 256>>>(x, g1, h16);
    // 4: q,k,v (fp16, q pre-scaled)
    gemm_qkv_k<<<dim3(TB_D / 128, TB_M / 128, 3), 256, GEMM_SMEM>>>(
        h16, wq16, wk16, wv16, q16, k16, v16);
    // 5: attention -> o fp16
    attn_kernel<<<dim3(TB_S / 128, TB_H, TB_B), 256, AT_SMEM>>>(q16, k16, v16, o16);
    // 6: x2 = o @ wo^T + x   <-- ncu -s 5 -c 1 captures this launch
    gemm_res_k<<<dim3(TB_D / 128, TB_M / 128), 256, GEMM_SMEM>>>(
        o16, wo16, x, x2, TB_D, TB_D);
    // 7: h2 = rmsnorm(x2, g2) -> fp16
    rmsnorm_h_kernel<<<TB_M, 256>>>(x2, g2, h216);
    // 8: mid = gelu(h2 @ w1^T) -> fp16
    gemm_gelu_k<<<dim3(TB_FF / 128, TB_M / 128), 256, GEMM_SMEM>>>(
        h216, w116, mid16, TB_FF, TB_D);
    // 9: out = mid @ w2^T + x2
    gemm_res_k<<<dim3(TB_D / 128, TB_M / 128), 256, GEMM_SMEM>>>(
        mid16, w216, x2, out, TB_D, TB_FF);
}

// round 12
// speedup vs baseline: 1.0692x; 1.0692x over previous
#include <cuda_runtime.h>
#include <cuda_fp16.h>
#include <math.h>
#include <stdint.h>

#define TB_B  2
#define TB_S  2048
#define TB_D  1024
#define TB_H  16
#define TB_DH 64
#define TB_FF 4096
#define TB_M  4096

// ---------------- scratch (no allocations allowed) ----------------
static __device__ float  g_x2[TB_M * TB_D];
static __device__ __half g_h16 [TB_M * TB_D];
static __device__ __half g_q16 [TB_M * TB_D];
static __device__ __half g_k16 [TB_M * TB_D];
static __device__ __half g_v16 [TB_M * TB_D];
static __device__ __half g_o16 [TB_M * TB_D];
static __device__ __half g_h216[TB_M * TB_D];
static __device__ __half g_mid16[(size_t)TB_M * TB_FF];
static __device__ __half g_wq16[TB_D * TB_D];
static __device__ __half g_wk16[TB_D * TB_D];
static __device__ __half g_wv16[TB_D * TB_D];
static __device__ __half g_wo16[TB_D * TB_D];
static __device__ __half g_w116[TB_FF * TB_D];
static __device__ __half g_w216[TB_D * TB_FF];

// ---------------- helpers ----------------
static __device__ __forceinline__ uint32_t smem_u32(const void* p) {
    uint32_t a;
    asm("{ .reg .u64 t; cvta.to.shared.u64 t, %1; cvt.u32.u64 %0, t; }" : "=r"(a) : "l"(p));
    return a;
}
static __device__ __forceinline__ void cp16(uint32_t d, const void* s) {
    asm volatile("cp.async.cg.shared.global [%0], [%1], 16;" :: "r"(d), "l"(s) : "memory");
}
#define CP_COMMIT()  asm volatile("cp.async.commit_group;" ::: "memory")
#define CP_WAIT(n)   asm volatile("cp.async.wait_group %0;" :: "n"(n) : "memory")

#define LDSM4(r0, r1, r2, r3, addr) \
    asm volatile("ldmatrix.sync.aligned.m8n8.x4.shared.b16 {%0,%1,%2,%3}, [%4];" \
                 : "=r"(r0), "=r"(r1), "=r"(r2), "=r"(r3) : "r"(addr))

#define LDSM4T(r0, r1, r2, r3, addr) \
    asm volatile("ldmatrix.sync.aligned.m8n8.x4.trans.shared.b16 {%0,%1,%2,%3}, [%4];" \
                 : "=r"(r0), "=r"(r1), "=r"(r2), "=r"(r3) : "r"(addr))

#define MMAF16(d, a, b0v, b1v) \
    asm volatile("mma.sync.aligned.m16n8k16.row.col.f32.f16.f16.f32 " \
                 "{%0,%1,%2,%3}, {%4,%5,%6,%7}, {%8,%9}, {%0,%1,%2,%3};" \
                 : "+f"((d)[0]), "+f"((d)[1]), "+f"((d)[2]), "+f"((d)[3]) \
                 : "r"((a)[0]), "r"((a)[1]), "r"((a)[2]), "r"((a)[3]), \
                   "r"(b0v), "r"(b1v))

static __device__ __forceinline__ float gelu_f(float x) {
    return 0.5f * x * (1.0f + erff(x * 0.70710678118654752440f));
}
static __device__ __forceinline__ uint32_t pack_h2(float a, float b) {
    __half2 h = __floats2half2_rn(a, b);
    return *(uint32_t*)&h;
}

// ---------------- weight convert kernels (fp32 -> fp16) ----------------
static __device__ __forceinline__ void conv_one(
    const float* __restrict__ s, __half* __restrict__ d, size_t i)
{
    const float4 v = ((const float4*)s)[i];
    ((__half2*)d)[i * 2]     = __floats2half2_rn(v.x, v.y);
    ((__half2*)d)[i * 2 + 1] = __floats2half2_rn(v.z, v.w);
}

__global__ void __launch_bounds__(256) conv4_kernel(
    const float* wq, __half* wq16, const float* wk, __half* wk16,
    const float* wv, __half* wv16, const float* wo, __half* wo16)
{
    const int which = blockIdx.x >> 10;
    const size_t i  = (size_t)(blockIdx.x & 1023) * 256 + threadIdx.x;
    if (which == 0)      conv_one(wq, wq16, i);
    else if (which == 1) conv_one(wk, wk16, i);
    else if (which == 2) conv_one(wv, wv16, i);
    else                 conv_one(wo, wo16, i);
}

__global__ void __launch_bounds__(256) convFF_kernel(
    const float* w1, __half* w116, const float* w2, __half* w216)
{
    const int which = blockIdx.x >> 12;
    const size_t i  = (size_t)(blockIdx.x & 4095) * 256 + threadIdx.x;
    if (which == 0) conv_one(w1, w116, i);
    else            conv_one(w2, w216, i);
}

// ---------------- rmsnorm -> fp16 ----------------
__global__ void __launch_bounds__(256) rmsnorm_h_kernel(
    const float* __restrict__ x, const float* __restrict__ g, __half* __restrict__ oh)
{
    const int row = blockIdx.x;
    const int tid = threadIdx.x;
    const float4 xv = ((const float4*)(x + (size_t)row * TB_D))[tid];
    float ss = xv.x * xv.x + xv.y * xv.y + xv.z * xv.z + xv.w * xv.w;
    #pragma unroll
    for (int off = 16; off; off >>= 1)
        ss += __shfl_xor_sync(0xffffffffu, ss, off);
    __shared__ float ws[8];
    __shared__ float s_scale;
    const int wid = tid >> 5, lane = tid & 31;
    if (lane == 0) ws[wid] = ss;
    __syncthreads();
    if (tid == 0) {
        float t = 0.f;
        #pragma unroll
        for (int i = 0; i < 8; i++) t += ws[i];
        s_scale = rsqrtf(t * (1.0f / (float)TB_D) + 1e-5f);
    }
    __syncthreads();
    const float sc = s_scale;
    const float4 gv = ((const float4*)g)[tid];
    const size_t o = (size_t)row * TB_D + tid * 4;
    *(__half2*)(oh + o)     = __floats2half2_rn(xv.x * gv.x * sc, xv.y * gv.y * sc);
    *(__half2*)(oh + o + 2) = __floats2half2_rn(xv.z * gv.z * sc, xv.w * gv.w * sc);
}

// ---------------- fp16 GEMM, 128x128 tile, 256 threads (R10 core) ----------------
#define ARR_BYTES   (128 * 144)
#define STAGE_BYTES (2 * ARR_BYTES)             // 36864 (A + B)
#define N_STAGES    3
#define GEMM_SMEM   (N_STAGES * STAGE_BYTES)    // 110592

template<int EPI>   // 1=gelu->fp16, 2=+res fp32, 3=fp16 scaled
static __device__ __forceinline__ void tc_gemm_core(
    const __half* __restrict__ A, const __half* __restrict__ B,
    const float* __restrict__ res, float* __restrict__ Cf,
    __half* __restrict__ Ch, float oscale,
    int N, int K)
{
    extern __shared__ char smc[];
    const uint32_t sb  = smem_u32(smc);
    const int tid  = threadIdx.x;
    const int lane = tid & 31;
    const int wm   = (tid >> 5) >> 2;     // 0..1
    const int wn   = (tid >> 5) & 3;      // 0..3
    const int bm   = blockIdx.y * 128;
    const int bn   = blockIdx.x * 128;
    const int nch  = K >> 6;

    auto load_chunk = [&](int kc, int st) {
        const uint32_t db  = sb + (uint32_t)st * STAGE_BYTES;
        const int kof = kc * 64;
        #pragma unroll
        for (int it = 0; it < 4; ++it) {
            const int g  = tid + it * 256;
            const int r  = g >> 3, gc = g & 7;
            const uint32_t off = (uint32_t)(r * 144 + gc * 16);
            cp16(db + off,             A + (size_t)(bm + r) * K + kof + gc * 8);
            cp16(db + ARR_BYTES + off, B + (size_t)(bn + r) * K + kof + gc * 8);
        }
        CP_COMMIT();
    };

    float acc[4][4][4];
    #pragma unroll
    for (int mi = 0; mi < 4; mi++)
        #pragma unroll
        for (int ni = 0; ni < 4; ni++)
            #pragma unroll
            for (int r = 0; r < 4; r++) acc[mi][ni][r] = 0.f;

    load_chunk(0, 0);
    if (nch > 1) load_chunk(1, 1);
    if (nch > 2) load_chunk(2, 2);

    const uint32_t aRow = (uint32_t)(wm * 64 + (lane & 15));
    const uint32_t aCol = (uint32_t)((lane >> 4) * 8);
    const int grp = lane >> 3, r8 = lane & 7;
    const uint32_t bRow = (uint32_t)(wn * 32 + (grp >> 1) * 8 + r8);
    const uint32_t bCol = (uint32_t)((grp & 1) * 8);

    for (int i = 0; i < nch; ++i) {
        const int p = i % N_STAGES;
        if (i + 2 < nch)      CP_WAIT(2);
        else if (i + 1 < nch) CP_WAIT(1);
        else                  CP_WAIT(0);
        __syncthreads();

        const uint32_t dA = sb + (uint32_t)p * STAGE_BYTES;
        const uint32_t dB = dA + ARR_BYTES;

        #pragma unroll
        for (int ks = 0; ks < 4; ++ks) {
            uint32_t a[4][4], b[4][2];
            const uint32_t kc2 = (uint32_t)(ks * 16) * 2;
            #pragma unroll
            for (int mi = 0; mi < 4; mi++) {
                const uint32_t ao = (aRow + mi * 16) * 144 + kc2 + aCol * 2;
                LDSM4(a[mi][0], a[mi][1], a[mi][2], a[mi][3], dA + ao);
            }
            #pragma unroll
            for (int nj = 0; nj < 2; nj++) {
                const uint32_t bo = (bRow + nj * 16) * 144 + kc2 + bCol * 2;
                LDSM4(b[nj*2][0], b[nj*2][1], b[nj*2+1][0], b[nj*2+1][1], dB + bo);
            }
            #pragma unroll
            for (int mi = 0; mi < 4; mi++)
                #pragma unroll
                for (int ni = 0; ni < 4; ni++)
                    MMAF16(acc[mi][ni], a[mi], b[ni][0], b[ni][1]);
        }
        __syncthreads();
        if (i + N_STAGES < nch) load_chunk(i + N_STAGES, p);
    }

    const int rq = lane >> 2, cq = (lane & 3) * 2;
    #pragma unroll
    for (int mi = 0; mi < 4; mi++) {
        #pragma unroll
        for (int ni = 0; ni < 4; ni++) {
            const int row0 = bm + wm * 64 + mi * 16 + rq;
            const int col  = bn + wn * 32 + ni * 8 + cq;
            #pragma unroll
            for (int half = 0; half < 2; half++) {
                const int row = row0 + half * 8;
                const size_t go = (size_t)row * N + col;
                const float v0 = acc[mi][ni][half * 2 + 0];
                const float v1 = acc[mi][ni][half * 2 + 1];
                if (EPI == 2) {
                    const float2 rv = *(const float2*)(res + go);
                    float2 v; v.x = v0 + rv.x; v.y = v1 + rv.y;
                    *(float2*)(Cf + go) = v;
                } else if (EPI == 3) {
                    *(__half2*)(Ch + go) = __floats2half2_rn(v0 * oscale, v1 * oscale);
                } else {
                    *(__half2*)(Ch + go) = __floats2half2_rn(gelu_f(v0), gelu_f(v1));
                }
            }
        }
    }
}

__global__ void __launch_bounds__(256, 2) gemm_qkv_k(
    const __half* A,
    const __half* wq, const __half* wk, const __half* wv,
    __half* q, __half* k, __half* v)
{
    const __half* B; __half* C; float sc;
    if (blockIdx.z == 0)      { B = wq; C = q; sc = 0.125f; }
    else if (blockIdx.z == 1) { B = wk; C = k; sc = 1.0f; }
    else                      { B = wv; C = v; sc = 1.0f; }
    tc_gemm_core<3>(A, B, nullptr, nullptr, C, sc, TB_D, TB_D);
}
__global__ void __launch_bounds__(256, 2) gemm_res_k(
    const __half* A, const __half* B,
    const float* res, float* C, int N, int K)
{
    tc_gemm_core<2>(A, B, res, C, nullptr, 1.f, N, K);
}

// ---------------- FFN1 GEMM: 128x256 tile, 8 warps of 64x64, 3-stage ----------------
// MMA:LDSM = 32:8 per ks (ratio 4:1). 1 CTA/SM (~200 regs, 166KB smem).
#define ARR_A256   (128 * 144)                    // 18432
#define ARR_B256   (256 * 144)                    // 36864
#define STAGE256   (ARR_A256 + ARR_B256)          // 55296
#define SMEM256    (3 * STAGE256)                 // 165888

__global__ void __launch_bounds__(256, 1) gemm_gelu256_k(
    const __half* __restrict__ A, const __half* __restrict__ B,
    __half* __restrict__ C, int N, int K)
{
    extern __shared__ char smc[];
    const uint32_t sb  = smem_u32(smc);
    const int tid  = threadIdx.x;
    const int lane = tid & 31;
    const int wm   = (tid >> 5) >> 2;     // 0..1 -> 64-row band
    const int wn   = (tid >> 5) & 3;      // 0..3 -> 64-col band
    const int bm   = blockIdx.y * 128;
    const int bn   = blockIdx.x * 256;
    const int nch  = K >> 6;

    auto load_chunk = [&](int kc, int st) {
        const uint32_t db = sb + (uint32_t)st * STAGE256;
        const uint32_t dB = db + ARR_A256;
        const int kof = kc * 64;
        #pragma unroll
        for (int it = 0; it < 4; ++it) {          // A: 1024 granules
            const int g  = tid + it * 256;
            const int r  = g >> 3, gc = g & 7;
            cp16(db + (uint32_t)(r * 144 + gc * 16),
                 A + (size_t)(bm + r) * K + kof + gc * 8);
        }
        #pragma unroll
        for (int it = 0; it < 8; ++it) {          // B: 2048 granules
            const int g  = tid + it * 256;
            const int r  = g >> 3, gc = g & 7;
            cp16(dB + (uint32_t)(r * 144 + gc * 16),
                 B + (size_t)(bn + r) * K + kof + gc * 8);
        }
        CP_COMMIT();
    };

    float acc[4][8][4];
    #pragma unroll
    for (int mi = 0; mi < 4; mi++)
        #pragma unroll
        for (int ni = 0; ni < 8; ni++)
            #pragma unroll
            for (int r = 0; r < 4; r++) acc[mi][ni][r] = 0.f;

    load_chunk(0, 0);
    if (nch > 1) load_chunk(1, 1);
    if (nch > 2) load_chunk(2, 2);

    const uint32_t aRow = (uint32_t)(wm * 64 + (lane & 15));
    const uint32_t aCol = (uint32_t)((lane >> 4) * 8);
    const int grp = lane >> 3, r8 = lane & 7;
    const uint32_t bRow = (uint32_t)(wn * 64 + (grp >> 1) * 8 + r8);
    const uint32_t bCol = (uint32_t)((grp & 1) * 8);

    for (int i = 0; i < nch; ++i) {
        const int p = i % 3;
        if (i + 2 < nch)      CP_WAIT(2);
        else if (i + 1 < nch) CP_WAIT(1);
        else                  CP_WAIT(0);
        __syncthreads();

        const uint32_t dA = sb + (uint32_t)p * STAGE256;
        const uint32_t dB = dA + ARR_A256;

        #pragma unroll
        for (int ks = 0; ks < 4; ++ks) {
            uint32_t a[4][4], b[8][2];
            const uint32_t kc2 = (uint32_t)(ks * 16) * 2;
            #pragma unroll
            for (int mi = 0; mi < 4; mi++) {
                const uint32_t ao = (aRow + mi * 16) * 144 + kc2 + aCol * 2;
                LDSM4(a[mi][0], a[mi][1], a[mi][2], a[mi][3], dA + ao);
            }
            #pragma unroll
            for (int nj = 0; nj < 4; nj++) {
                const uint32_t bo = (bRow + nj * 16) * 144 + kc2 + bCol * 2;
                LDSM4(b[nj*2][0], b[nj*2][1], b[nj*2+1][0], b[nj*2+1][1], dB + bo);
            }
            #pragma unroll
            for (int mi = 0; mi < 4; mi++)
                #pragma unroll
                for (int ni = 0; ni < 8; ni++)
                    MMAF16(acc[mi][ni], a[mi], b[ni][0], b[ni][1]);
        }
        __syncthreads();
        if (i + 3 < nch) load_chunk(i + 3, p);
    }

    const int rq = lane >> 2, cq = (lane & 3) * 2;
    #pragma unroll
    for (int mi = 0; mi < 4; mi++) {
        #pragma unroll
        for (int ni = 0; ni < 8; ni++) {
            const int row0 = bm + wm * 64 + mi * 16 + rq;
            const int col  = bn + wn * 64 + ni * 8 + cq;
            #pragma unroll
            for (int half = 0; half < 2; half++) {
                const int row = row0 + half * 8;
                const size_t go = (size_t)row * N + col;
                *(__half2*)(C + go) = __floats2half2_rn(
                    gelu_f(acc[mi][ni][half * 2 + 0]),
                    gelu_f(acc[mi][ni][half * 2 + 1]));
            }
        }
    }
}

// ---------------- fp16 tensor-core causal flash attention ----------------
#define AT_LD    72
#define AT_QB    (128 * AT_LD * 2)
#define AT_KB    (64 * AT_LD * 2)
#define AT_STB   (2 * AT_KB)
#define AT_SMEM  (AT_QB + 2 * AT_STB)

__global__ void __launch_bounds__(256, 2) attn_kernel(
    const __half* __restrict__ Qg, const __half* __restrict__ Kg,
    const __half* __restrict__ Vg, __half* __restrict__ Og)
{
    extern __shared__ char smc[];
    const uint32_t sb = smem_u32(smc);
    const uint32_t sQ = sb;

    const int qt   = gridDim.x - 1 - blockIdx.x;
    const int h    = blockIdx.y;
    const int b    = blockIdx.z;
    const int tid  = threadIdx.x;
    const int lane = tid & 31;
    const int warp = tid >> 5;

    const int qbase   = qt * 128;
    const size_t tokQ = (size_t)b * TB_S + qbase;
    const size_t tokK = (size_t)b * TB_S;
    const int hoff    = h * TB_DH;
    const int jtmax   = 2 * qt + 1;

    auto cpQ = [&]() {
        #pragma unroll
        for (int it = 0; it < 4; ++it) {
            const int g = tid + it * 256;
            const int r = g >> 3, c = g & 7;
            cp16(sQ + (uint32_t)(r * 144 + c * 16),
                 Qg + (tokQ + r) * TB_D + hoff + c * 8);
        }
        CP_COMMIT();
    };
    auto cpKV = [&](int jt, int st) {
        const uint32_t sK = sb + AT_QB + (uint32_t)st * AT_STB;
        const uint32_t sV = sK + AT_KB;
        const size_t rowb = tokK + (size_t)jt * 64;
        #pragma unroll
        for (int it = 0; it < 2; ++it) {
            const int g = tid + it * 256;
            const int r = g >> 3, c = g & 7;
            const uint32_t off = (uint32_t)(r * 144 + c * 16);
            const size_t so = (rowb + r) * TB_D + hoff + c * 8;
            cp16(sK + off, Kg + so);
            cp16(sV + off, Vg + so);
        }
        CP_COMMIT();
    };

    cpQ();
    cpKV(0, 0);
    cpKV(1, 1);

    const uint32_t aRow = (uint32_t)(warp * 16 + (lane & 15));
    const uint32_t aCol = (uint32_t)((lane >> 4) * 8);
    const int grp = lane >> 3, r8 = lane & 7;
    const uint32_t bRowB = (uint32_t)((grp >> 1) * 8 + r8);
    const uint32_t bColB = (uint32_t)((grp & 1) * 8);
    const uint32_t vRow = (uint32_t)(lane & 15);
    const uint32_t vCol = (uint32_t)((lane >> 4) * 8);

    uint32_t qa[4][4];
    float o[8][4];
    #pragma unroll
    for (int nt = 0; nt < 8; nt++)
        #pragma unroll
        for (int r = 0; r < 4; r++) o[nt][r] = 0.f;
    float m0 = -1e30f, m1 = -1e30f, l0 = 0.f, l1 = 0.f;

    const int rloc0 = lane >> 2;
    const int growA = qbase + warp * 16 + rloc0;

    for (int jt = 0; jt <= jtmax; ++jt) {
        const int st = jt & 1;
        if (jt + 1 <= jtmax) CP_WAIT(1); else CP_WAIT(0);
        __syncthreads();

        if (jt == 0) {
            #pragma unroll
            for (int ks = 0; ks < 4; ++ks) {
                const uint32_t ao = sQ + (aRow * 144 + (uint32_t)(ks * 16) * 2 + aCol * 2);
                LDSM4(qa[ks][0], qa[ks][1], qa[ks][2], qa[ks][3], ao);
            }
        }

        const uint32_t sK = sb + AT_QB + (uint32_t)st * AT_STB;
        const uint32_t sV = sK + AT_KB;

        float s[8][4];
        #pragma unroll
        for (int nt = 0; nt < 8; nt++)
            #pragma unroll
            for (int r = 0; r < 4; r++) s[nt][r] = 0.f;

        #pragma unroll
        for (int ks = 0; ks < 4; ++ks) {
            uint32_t kb[8][2];
            #pragma unroll
            for (int nt16 = 0; nt16 < 4; nt16++) {
                const uint32_t bo = sK + ((bRowB + nt16 * 16) * 144 + (uint32_t)(ks * 16) * 2 + bColB * 2);
                LDSM4(kb[nt16*2][0], kb[nt16*2][1], kb[nt16*2+1][0], kb[nt16*2+1][1], bo);
            }
            #pragma unroll
            for (int nt = 0; nt < 8; nt++)
                MMAF16(s[nt], qa[ks], kb[nt][0], kb[nt][1]);
        }

        if (jt * 64 + 63 > qbase + warp * 16) {
            const int colb = jt * 64 + 2 * (lane & 3);
            #pragma unroll
            for (int nt = 0; nt < 8; nt++) {
                const int c0 = colb + nt * 8, c1 = c0 + 1;
                if (c0 > growA)     s[nt][0] = -1e30f;
                if (c1 > growA)     s[nt][1] = -1e30f;
                if (c0 > growA + 8) s[nt][2] = -1e30f;
                if (c1 > growA + 8) s[nt][3] = -1e30f;
            }
        }

        float mx0 = -1e30f, mx1 = -1e30f;
        #pragma unroll
        for (int nt = 0; nt < 8; nt++) {
            mx0 = fmaxf(mx0, fmaxf(s[nt][0], s[nt][1]));
            mx1 = fmaxf(mx1, fmaxf(s[nt][2], s[nt][3]));
        }
        #pragma unroll
        for (int off = 1; off <= 2; off <<= 1) {
            mx0 = fmaxf(mx0, __shfl_xor_sync(0xffffffffu, mx0, off, 4));
            mx1 = fmaxf(mx1, __shfl_xor_sync(0xffffffffu, mx1, off, 4));
        }
        const float mn0 = fmaxf(m0, mx0), mn1 = fmaxf(m1, mx1);
        const float al0 = exp2f((m0 - mn0) * 1.44269504f);
        const float al1 = exp2f((m1 - mn1) * 1.44269504f);
        m0 = mn0; m1 = mn1;
        float ps0 = 0.f, ps1 = 0.f;
        #pragma unroll
        for (int nt = 0; nt < 8; nt++) {
            s[nt][0] = exp2f((s[nt][0] - mn0) * 1.44269504f);
            s[nt][1] = exp2f((s[nt][1] - mn0) * 1.44269504f);
            s[nt][2] = exp2f((s[nt][2] - mn1) * 1.44269504f);
            s[nt][3] = exp2f((s[nt][3] - mn1) * 1.44269504f);
            ps0 += s[nt][0] + s[nt][1];
            ps1 += s[nt][2] + s[nt][3];
        }
        #pragma unroll
        for (int off = 1; off <= 2; off <<= 1) {
            ps0 += __shfl_xor_sync(0xffffffffu, ps0, off, 4);
            ps1 += __shfl_xor_sync(0xffffffffu, ps1, off, 4);
        }
        l0 = l0 * al0 + ps0;
        l1 = l1 * al1 + ps1;
        #pragma unroll
        for (int nt = 0; nt < 8; nt++) {
            o[nt][0] *= al0; o[nt][1] *= al0;
            o[nt][2] *= al1; o[nt][3] *= al1;
        }

        uint32_t pa[4][4];
        #pragma unroll
        for (int j = 0; j < 4; j++) {
            pa[j][0] = pack_h2(s[2*j][0],   s[2*j][1]);
            pa[j][1] = pack_h2(s[2*j][2],   s[2*j][3]);
            pa[j][2] = pack_h2(s[2*j+1][0], s[2*j+1][1]);
            pa[j][3] = pack_h2(s[2*j+1][2], s[2*j+1][3]);
        }

        #pragma unroll
        for (int ks = 0; ks < 4; ++ks) {
            #pragma unroll
            for (int ntp = 0; ntp < 4; ntp++) {
                uint32_t v0, v1, v2, v3;
                const uint32_t vo = sV + ((vRow + ks * 16) * 144 + (vCol + ntp * 16) * 2);
                LDSM4T(v0, v1, v2, v3, vo);
                MMAF16(o[ntp*2],     pa[ks], v0, v1);
                MMAF16(o[ntp*2+1],   pa[ks], v2, v3);
            }
        }

        __syncthreads();
        if (jt + 2 <= jtmax) cpKV(jt + 2, st);
    }

    const float inv0 = 1.0f / l0, inv1 = 1.0f / l1;
    const size_t row0 = tokQ + warp * 16 + rloc0;
    const int colb = hoff + 2 * (lane & 3);
    #pragma unroll
    for (int nt = 0; nt < 8; nt++) {
        *(__half2*)(Og + row0 * TB_D + colb + nt * 8) =
            __floats2half2_rn(o[nt][0] * inv0, o[nt][1] * inv0);
        *(__half2*)(Og + (row0 + 8) * TB_D + colb + nt * 8) =
            __floats2half2_rn(o[nt][2] * inv1, o[nt][3] * inv1);
    }
}

// ---------------- launch ----------------
extern "C" void kernel_launch(void* const* d_in, const int* in_sizes, int n_in,
                              void* d_out, int out_size)
{
    const float* x  = (const float*)d_in[0];
    const float* wq = (const float*)d_in[1];
    const float* wk = (const float*)d_in[2];
    const float* wv = (const float*)d_in[3];
    const float* wo = (const float*)d_in[4];
    const float* w1 = (const float*)d_in[5];
    const float* w2 = (const float*)d_in[6];
    const float* g1 = (const float*)d_in[7];
    const float* g2 = (const float*)d_in[8];
    float* out = (float*)d_out;

    float *x2;
    __half *h16, *q16, *k16, *v16, *o16, *h216, *mid16;
    __half *wq16, *wk16, *wv16, *wo16, *w116, *w216;
    cudaGetSymbolAddress((void**)&x2,    g_x2);
    cudaGetSymbolAddress((void**)&h16,   g_h16);
    cudaGetSymbolAddress((void**)&q16,   g_q16);
    cudaGetSymbolAddress((void**)&k16,   g_k16);
    cudaGetSymbolAddress((void**)&v16,   g_v16);
    cudaGetSymbolAddress((void**)&o16,   g_o16);
    cudaGetSymbolAddress((void**)&h216,  g_h216);
    cudaGetSymbolAddress((void**)&mid16, g_mid16);
    cudaGetSymbolAddress((void**)&wq16,  g_wq16);
    cudaGetSymbolAddress((void**)&wk16,  g_wk16);
    cudaGetSymbolAddress((void**)&wv16,  g_wv16);
    cudaGetSymbolAddress((void**)&wo16,  g_wo16);
    cudaGetSymbolAddress((void**)&w116,  g_w116);
    cudaGetSymbolAddress((void**)&w216,  g_w216);

    cudaFuncSetAttribute(gemm_qkv_k,     cudaFuncAttributeMaxDynamicSharedMemorySize, GEMM_SMEM);
    cudaFuncSetAttribute(gemm_res_k,     cudaFuncAttributeMaxDynamicSharedMemorySize, GEMM_SMEM);
    cudaFuncSetAttribute(gemm_gelu256_k, cudaFuncAttributeMaxDynamicSharedMemorySize, SMEM256);
    cudaFuncSetAttribute(attn_kernel,    cudaFuncAttributeMaxDynamicSharedMemorySize, AT_SMEM);

    // 1: attention-weight converts
    conv4_kernel<<<4096, 256>>>(wq, wq16, wk, wk16, wv, wv16, wo, wo16);
    // 2: FFN-weight converts
    convFF_kernel<<<8192, 256>>>(w1, w116, w2, w216);
    // 3: h = rmsnorm(x, g1) -> fp16
    rmsnorm_h_kernel<<<TB_M, 256>>>(x, g1, h16);
    // 4: q,k,v (fp16, q pre-scaled)
    gemm_qkv_k<<<dim3(TB_D / 128, TB_M / 128, 3), 256, GEMM_SMEM>>>(
        h16, wq16, wk16, wv16, q16, k16, v16);
    // 5: attention -> o fp16
    attn_kernel<<<dim3(TB_S / 128, TB_H, TB_B), 256, AT_SMEM>>>(q16, k16, v16, o16);
    // 6: x2 = o @ wo^T + x   <-- ncu -s 5 -c 1 captures this launch
    gemm_res_k<<<dim3(TB_D / 128, TB_M / 128), 256, GEMM_SMEM>>>(
        o16, wo16, x, x2, TB_D, TB_D);
    // 7: h2 = rmsnorm(x2, g2) -> fp16
    rmsnorm_h_kernel<<<TB_M, 256>>>(x2, g2, h216);
    // 8: mid = gelu(h2 @ w1^T) -> fp16  (128x256 tile, ratio 4:1)
    gemm_gelu256_k<<<dim3(TB_FF / 256, TB_M / 128), 256, SMEM256>>>(
        h216, w116, mid16, TB_FF, TB_D);
    // 9: out = mid @ w2^T + x2
    gemm_res_k<<<dim3(TB_D / 128, TB_M / 128), 256, GEMM_SMEM>>>(
        mid16, w216, x2, out, TB_D, TB_FF);
}

// round 14
// speedup vs baseline: 1.0693x; 1.0001x over previous
#include <cuda_runtime.h>
#include <cuda_fp16.h>
#include <math.h>
#include <stdint.h>

#define TB_B  2
#define TB_S  2048
#define TB_D  1024
#define TB_H  16
#define TB_DH 64
#define TB_FF 4096
#define TB_M  4096

// ---------------- scratch (no allocations allowed) ----------------
static __device__ float  g_x2[TB_M * TB_D];
static __device__ __half g_h16 [TB_M * TB_D];
static __device__ __half g_q16 [TB_M * TB_D];
static __device__ __half g_k16 [TB_M * TB_D];
static __device__ __half g_v16 [TB_M * TB_D];
static __device__ __half g_o16 [TB_M * TB_D];
static __device__ __half g_h216[TB_M * TB_D];
static __device__ __half g_mid16[(size_t)TB_M * TB_FF];
static __device__ __half g_wq16[TB_D * TB_D];
static __device__ __half g_wk16[TB_D * TB_D];
static __device__ __half g_wv16[TB_D * TB_D];
static __device__ __half g_wo16[TB_D * TB_D];
static __device__ __half g_w116[TB_FF * TB_D];
static __device__ __half g_w216[TB_D * TB_FF];

// ---------------- helpers ----------------
static __device__ __forceinline__ uint32_t smem_u32(const void* p) {
    uint32_t a;
    asm("{ .reg .u64 t; cvta.to.shared.u64 t, %1; cvt.u32.u64 %0, t; }" : "=r"(a) : "l"(p));
    return a;
}
static __device__ __forceinline__ void cp16(uint32_t d, const void* s) {
    asm volatile("cp.async.cg.shared.global [%0], [%1], 16;" :: "r"(d), "l"(s) : "memory");
}
#define CP_COMMIT()  asm volatile("cp.async.commit_group;" ::: "memory")
#define CP_WAIT(n)   asm volatile("cp.async.wait_group %0;" :: "n"(n) : "memory")

#define LDSM4(r0, r1, r2, r3, addr) \
    asm volatile("ldmatrix.sync.aligned.m8n8.x4.shared.b16 {%0,%1,%2,%3}, [%4];" \
                 : "=r"(r0), "=r"(r1), "=r"(r2), "=r"(r3) : "r"(addr))

#define LDSM4T(r0, r1, r2, r3, addr) \
    asm volatile("ldmatrix.sync.aligned.m8n8.x4.trans.shared.b16 {%0,%1,%2,%3}, [%4];" \
                 : "=r"(r0), "=r"(r1), "=r"(r2), "=r"(r3) : "r"(addr))

#define MMAF16(d, a, b0v, b1v) \
    asm volatile("mma.sync.aligned.m16n8k16.row.col.f32.f16.f16.f32 " \
                 "{%0,%1,%2,%3}, {%4,%5,%6,%7}, {%8,%9}, {%0,%1,%2,%3};" \
                 : "+f"((d)[0]), "+f"((d)[1]), "+f"((d)[2]), "+f"((d)[3]) \
                 : "r"((a)[0]), "r"((a)[1]), "r"((a)[2]), "r"((a)[3]), \
                   "r"(b0v), "r"(b1v))

static __device__ __forceinline__ float gelu_f(float x) {
    return 0.5f * x * (1.0f + erff(x * 0.70710678118654752440f));
}
static __device__ __forceinline__ uint32_t pack_h2(float a, float b) {
    __half2 h = __floats2half2_rn(a, b);
    return *(uint32_t*)&h;
}

// ---------------- weight convert kernels (fp32 -> fp16) ----------------
static __device__ __forceinline__ void conv_one(
    const float* __restrict__ s, __half* __restrict__ d, size_t i)
{
    const float4 v = ((const float4*)s)[i];
    ((__half2*)d)[i * 2]     = __floats2half2_rn(v.x, v.y);
    ((__half2*)d)[i * 2 + 1] = __floats2half2_rn(v.z, v.w);
}

__global__ void __launch_bounds__(256) conv4_kernel(
    const float* wq, __half* wq16, const float* wk, __half* wk16,
    const float* wv, __half* wv16, const float* wo, __half* wo16)
{
    const int which = blockIdx.x >> 10;
    const size_t i  = (size_t)(blockIdx.x & 1023) * 256 + threadIdx.x;
    if (which == 0)      conv_one(wq, wq16, i);
    else if (which == 1) conv_one(wk, wk16, i);
    else if (which == 2) conv_one(wv, wv16, i);
    else                 conv_one(wo, wo16, i);
}

__global__ void __launch_bounds__(256) convFF_kernel(
    const float* w1, __half* w116, const float* w2, __half* w216)
{
    const int which = blockIdx.x >> 12;
    const size_t i  = (size_t)(blockIdx.x & 4095) * 256 + threadIdx.x;
    if (which == 0) conv_one(w1, w116, i);
    else            conv_one(w2, w216, i);
}

// ---------------- rmsnorm -> fp16 ----------------
__global__ void __launch_bounds__(256) rmsnorm_h_kernel(
    const float* __restrict__ x, const float* __restrict__ g, __half* __restrict__ oh)
{
    const int row = blockIdx.x;
    const int tid = threadIdx.x;
    const float4 xv = ((const float4*)(x + (size_t)row * TB_D))[tid];
    float ss = xv.x * xv.x + xv.y * xv.y + xv.z * xv.z + xv.w * xv.w;
    #pragma unroll
    for (int off = 16; off; off >>= 1)
        ss += __shfl_xor_sync(0xffffffffu, ss, off);
    __shared__ float ws[8];
    __shared__ float s_scale;
    const int wid = tid >> 5, lane = tid & 31;
    if (lane == 0) ws[wid] = ss;
    __syncthreads();
    if (tid == 0) {
        float t = 0.f;
        #pragma unroll
        for (int i = 0; i < 8; i++) t += ws[i];
        s_scale = rsqrtf(t * (1.0f / (float)TB_D) + 1e-5f);
    }
    __syncthreads();
    const float sc = s_scale;
    const float4 gv = ((const float4*)g)[tid];
    const size_t o = (size_t)row * TB_D + tid * 4;
    *(__half2*)(oh + o)     = __floats2half2_rn(xv.x * gv.x * sc, xv.y * gv.y * sc);
    *(__half2*)(oh + o + 2) = __floats2half2_rn(xv.z * gv.z * sc, xv.w * gv.w * sc);
}

// ---------------- fp16 GEMM, 128x128 tile, 256 threads (R10 core) ----------------
#define ARR_BYTES   (128 * 144)
#define STAGE_BYTES (2 * ARR_BYTES)             // 36864 (A + B)
#define N_STAGES    3
#define GEMM_SMEM   (N_STAGES * STAGE_BYTES)    // 110592

template<int EPI>   // 1=gelu->fp16, 2=+res fp32, 3=fp16 scaled
static __device__ __forceinline__ void tc_gemm_core(
    const __half* __restrict__ A, const __half* __restrict__ B,
    const float* __restrict__ res, float* __restrict__ Cf,
    __half* __restrict__ Ch, float oscale,
    int N, int K)
{
    extern __shared__ char smc[];
    const uint32_t sb  = smem_u32(smc);
    const int tid  = threadIdx.x;
    const int lane = tid & 31;
    const int wm   = (tid >> 5) >> 2;     // 0..1
    const int wn   = (tid >> 5) & 3;      // 0..3
    const int bm   = blockIdx.y * 128;
    const int bn   = blockIdx.x * 128;
    const int nch  = K >> 6;

    auto load_chunk = [&](int kc, int st) {
        const uint32_t db  = sb + (uint32_t)st * STAGE_BYTES;
        const int kof = kc * 64;
        #pragma unroll
        for (int it = 0; it < 4; ++it) {
            const int g  = tid + it * 256;
            const int r  = g >> 3, gc = g & 7;
            const uint32_t off = (uint32_t)(r * 144 + gc * 16);
            cp16(db + off,             A + (size_t)(bm + r) * K + kof + gc * 8);
            cp16(db + ARR_BYTES + off, B + (size_t)(bn + r) * K + kof + gc * 8);
        }
        CP_COMMIT();
    };

    float acc[4][4][4];
    #pragma unroll
    for (int mi = 0; mi < 4; mi++)
        #pragma unroll
        for (int ni = 0; ni < 4; ni++)
            #pragma unroll
            for (int r = 0; r < 4; r++) acc[mi][ni][r] = 0.f;

    load_chunk(0, 0);
    if (nch > 1) load_chunk(1, 1);
    if (nch > 2) load_chunk(2, 2);

    const uint32_t aRow = (uint32_t)(wm * 64 + (lane & 15));
    const uint32_t aCol = (uint32_t)((lane >> 4) * 8);
    const int grp = lane >> 3, r8 = lane & 7;
    const uint32_t bRow = (uint32_t)(wn * 32 + (grp >> 1) * 8 + r8);
    const uint32_t bCol = (uint32_t)((grp & 1) * 8);

    for (int i = 0; i < nch; ++i) {
        const int p = i % N_STAGES;
        if (i + 2 < nch)      CP_WAIT(2);
        else if (i + 1 < nch) CP_WAIT(1);
        else                  CP_WAIT(0);
        __syncthreads();

        const uint32_t dA = sb + (uint32_t)p * STAGE_BYTES;
        const uint32_t dB = dA + ARR_BYTES;

        #pragma unroll
        for (int ks = 0; ks < 4; ++ks) {
            uint32_t a[4][4], b[4][2];
            const uint32_t kc2 = (uint32_t)(ks * 16) * 2;
            #pragma unroll
            for (int mi = 0; mi < 4; mi++) {
                const uint32_t ao = (aRow + mi * 16) * 144 + kc2 + aCol * 2;
                LDSM4(a[mi][0], a[mi][1], a[mi][2], a[mi][3], dA + ao);
            }
            #pragma unroll
            for (int nj = 0; nj < 2; nj++) {
                const uint32_t bo = (bRow + nj * 16) * 144 + kc2 + bCol * 2;
                LDSM4(b[nj*2][0], b[nj*2][1], b[nj*2+1][0], b[nj*2+1][1], dB + bo);
            }
            #pragma unroll
            for (int mi = 0; mi < 4; mi++)
                #pragma unroll
                for (int ni = 0; ni < 4; ni++)
                    MMAF16(acc[mi][ni], a[mi], b[ni][0], b[ni][1]);
        }
        __syncthreads();
        if (i + N_STAGES < nch) load_chunk(i + N_STAGES, p);
    }

    const int rq = lane >> 2, cq = (lane & 3) * 2;
    #pragma unroll
    for (int mi = 0; mi < 4; mi++) {
        #pragma unroll
        for (int ni = 0; ni < 4; ni++) {
            const int row0 = bm + wm * 64 + mi * 16 + rq;
            const int col  = bn + wn * 32 + ni * 8 + cq;
            #pragma unroll
            for (int half = 0; half < 2; half++) {
                const int row = row0 + half * 8;
                const size_t go = (size_t)row * N + col;
                const float v0 = acc[mi][ni][half * 2 + 0];
                const float v1 = acc[mi][ni][half * 2 + 1];
                if (EPI == 2) {
                    const float2 rv = *(const float2*)(res + go);
                    float2 v; v.x = v0 + rv.x; v.y = v1 + rv.y;
                    *(float2*)(Cf + go) = v;
                } else if (EPI == 3) {
                    *(__half2*)(Ch + go) = __floats2half2_rn(v0 * oscale, v1 * oscale);
                } else {
                    *(__half2*)(Ch + go) = __floats2half2_rn(gelu_f(v0), gelu_f(v1));
                }
            }
        }
    }
}

__global__ void __launch_bounds__(256, 2) gemm_qkv_k(
    const __half* A,
    const __half* wq, const __half* wk, const __half* wv,
    __half* q, __half* k, __half* v)
{
    const __half* B; __half* C; float sc;
    if (blockIdx.z == 0)      { B = wq; C = q; sc = 0.125f; }
    else if (blockIdx.z == 1) { B = wk; C = k; sc = 1.0f; }
    else                      { B = wv; C = v; sc = 1.0f; }
    tc_gemm_core<3>(A, B, nullptr, nullptr, C, sc, TB_D, TB_D);
}
__global__ void __launch_bounds__(256, 2) gemm_res_k(
    const __half* A, const __half* B,
    const float* res, float* C, int N, int K)
{
    tc_gemm_core<2>(A, B, res, C, nullptr, 1.f, N, K);
}

// ---------------- FFN1 GEMM: 128x256 tile, 8 warps of 64x64, 3-stage ----------------
#define ARR_A256   (128 * 144)                    // 18432
#define ARR_B256   (256 * 144)                    // 36864
#define STAGE256   (ARR_A256 + ARR_B256)          // 55296
#define SMEM256    (3 * STAGE256)                 // 165888

__global__ void __launch_bounds__(256, 1) gemm_gelu256_k(
    const __half* __restrict__ A, const __half* __restrict__ B,
    __half* __restrict__ C, int N, int K)
{
    extern __shared__ char smc[];
    const uint32_t sb  = smem_u32(smc);
    const int tid  = threadIdx.x;
    const int lane = tid & 31;
    const int wm   = (tid >> 5) >> 2;     // 0..1 -> 64-row band
    const int wn   = (tid >> 5) & 3;      // 0..3 -> 64-col band
    const int bm   = blockIdx.y * 128;
    const int bn   = blockIdx.x * 256;
    const int nch  = K >> 6;

    auto load_chunk = [&](int kc, int st) {
        const uint32_t db = sb + (uint32_t)st * STAGE256;
        const uint32_t dB = db + ARR_A256;
        const int kof = kc * 64;
        #pragma unroll
        for (int it = 0; it < 4; ++it) {          // A: 1024 granules
            const int g  = tid + it * 256;
            const int r  = g >> 3, gc = g & 7;
            cp16(db + (uint32_t)(r * 144 + gc * 16),
                 A + (size_t)(bm + r) * K + kof + gc * 8);
        }
        #pragma unroll
        for (int it = 0; it < 8; ++it) {          // B: 2048 granules
            const int g  = tid + it * 256;
            const int r  = g >> 3, gc = g & 7;
            cp16(dB + (uint32_t)(r * 144 + gc * 16),
                 B + (size_t)(bn + r) * K + kof + gc * 8);
        }
        CP_COMMIT();
    };

    float acc[4][8][4];
    #pragma unroll
    for (int mi = 0; mi < 4; mi++)
        #pragma unroll
        for (int ni = 0; ni < 8; ni++)
            #pragma unroll
            for (int r = 0; r < 4; r++) acc[mi][ni][r] = 0.f;

    load_chunk(0, 0);
    if (nch > 1) load_chunk(1, 1);
    if (nch > 2) load_chunk(2, 2);

    const uint32_t aRow = (uint32_t)(wm * 64 + (lane & 15));
    const uint32_t aCol = (uint32_t)((lane >> 4) * 8);
    const int grp = lane >> 3, r8 = lane & 7;
    const uint32_t bRow = (uint32_t)(wn * 64 + (grp >> 1) * 8 + r8);
    const uint32_t bCol = (uint32_t)((grp & 1) * 8);

    for (int i = 0; i < nch; ++i) {
        const int p = i % 3;
        if (i + 2 < nch)      CP_WAIT(2);
        else if (i + 1 < nch) CP_WAIT(1);
        else                  CP_WAIT(0);
        __syncthreads();

        const uint32_t dA = sb + (uint32_t)p * STAGE256;
        const uint32_t dB = dA + ARR_A256;

        #pragma unroll
        for (int ks = 0; ks < 4; ++ks) {
            uint32_t a[4][4], b[8][2];
            const uint32_t kc2 = (uint32_t)(ks * 16) * 2;
            #pragma unroll
            for (int mi = 0; mi < 4; mi++) {
                const uint32_t ao = (aRow + mi * 16) * 144 + kc2 + aCol * 2;
                LDSM4(a[mi][0], a[mi][1], a[mi][2], a[mi][3], dA + ao);
            }
            #pragma unroll
            for (int nj = 0; nj < 4; nj++) {
                const uint32_t bo = (bRow + nj * 16) * 144 + kc2 + bCol * 2;
                LDSM4(b[nj*2][0], b[nj*2][1], b[nj*2+1][0], b[nj*2+1][1], dB + bo);
            }
            #pragma unroll
            for (int mi = 0; mi < 4; mi++)
                #pragma unroll
                for (int ni = 0; ni < 8; ni++)
                    MMAF16(acc[mi][ni], a[mi], b[ni][0], b[ni][1]);
        }
        __syncthreads();
        if (i + 3 < nch) load_chunk(i + 3, p);
    }

    const int rq = lane >> 2, cq = (lane & 3) * 2;
    #pragma unroll
    for (int mi = 0; mi < 4; mi++) {
        #pragma unroll
        for (int ni = 0; ni < 8; ni++) {
            const int row0 = bm + wm * 64 + mi * 16 + rq;
            const int col  = bn + wn * 64 + ni * 8 + cq;
            #pragma unroll
            for (int half = 0; half < 2; half++) {
                const int row = row0 + half * 8;
                const size_t go = (size_t)row * N + col;
                *(__half2*)(C + go) = __floats2half2_rn(
                    gelu_f(acc[mi][ni][half * 2 + 0]),
                    gelu_f(acc[mi][ni][half * 2 + 1]));
            }
        }
    }
}

// ---------------- fp16 tensor-core causal flash attention ----------------
#define AT_LD    72
#define AT_QB    (128 * AT_LD * 2)
#define AT_KB    (64 * AT_LD * 2)
#define AT_STB   (2 * AT_KB)
#define AT_SMEM  (AT_QB + 2 * AT_STB)

__global__ void __launch_bounds__(256, 1) attn_kernel(
    const __half* __restrict__ Qg, const __half* __restrict__ Kg,
    const __half* __restrict__ Vg, __half* __restrict__ Og)
{
    extern __shared__ char smc[];
    const uint32_t sb = smem_u32(smc);
    const uint32_t sQ = sb;

    const int qt   = gridDim.x - 1 - blockIdx.x;
    const int h    = blockIdx.y;
    const int b    = blockIdx.z;
    const int tid  = threadIdx.x;
    const int lane = tid & 31;
    const int warp = tid >> 5;

    const int qbase   = qt * 128;
    const size_t tokQ = (size_t)b * TB_S + qbase;
    const size_t tokK = (size_t)b * TB_S;
    const int hoff    = h * TB_DH;
    const int jtmax   = 2 * qt + 1;

    auto cpQ = [&]() {
        #pragma unroll
        for (int it = 0; it < 4; ++it) {
            const int g = tid + it * 256;
            const int r = g >> 3, c = g & 7;
            cp16(sQ + (uint32_t)(r * 144 + c * 16),
                 Qg + (tokQ + r) * TB_D + hoff + c * 8);
        }
        CP_COMMIT();
    };
    auto cpKV = [&](int jt, int st) {
        const uint32_t sK = sb + AT_QB + (uint32_t)st * AT_STB;
        const uint32_t sV = sK + AT_KB;
        const size_t rowb = tokK + (size_t)jt * 64;
        #pragma unroll
        for (int it = 0; it < 2; ++it) {
            const int g = tid + it * 256;
            const int r = g >> 3, c = g & 7;
            const uint32_t off = (uint32_t)(r * 144 + c * 16);
            const size_t so = (rowb + r) * TB_D + hoff + c * 8;
            cp16(sK + off, Kg + so);
            cp16(sV + off, Vg + so);
        }
        CP_COMMIT();
    };

    cpQ();
    cpKV(0, 0);
    cpKV(1, 1);

    const uint32_t aRow = (uint32_t)(warp * 16 + (lane & 15));
    const uint32_t aCol = (uint32_t)((lane >> 4) * 8);
    const int grp = lane >> 3, r8 = lane & 7;
    const uint32_t bRowB = (uint32_t)((grp >> 1) * 8 + r8);
    const uint32_t bColB = (uint32_t)((grp & 1) * 8);
    const uint32_t vRow = (uint32_t)(lane & 15);
    const uint32_t vCol = (uint32_t)((lane >> 4) * 8);

    uint32_t qa[4][4];
    float o[8][4];
    #pragma unroll
    for (int nt = 0; nt < 8; nt++)
        #pragma unroll
        for (int r = 0; r < 4; r++) o[nt][r] = 0.f;
    float m0 = -1e30f, m1 = -1e30f, l0 = 0.f, l1 = 0.f;

    const int rloc0 = lane >> 2;
    const int growA = qbase + warp * 16 + rloc0;

    for (int jt = 0; jt <= jtmax; ++jt) {
        const int st = jt & 1;
        if (jt + 1 <= jtmax) CP_WAIT(1); else CP_WAIT(0);
        __syncthreads();

        if (jt == 0) {
            #pragma unroll
            for (int ks = 0; ks < 4; ++ks) {
                const uint32_t ao = sQ + (aRow * 144 + (uint32_t)(ks * 16) * 2 + aCol * 2);
                LDSM4(qa[ks][0], qa[ks][1], qa[ks][2], qa[ks][3], ao);
            }
        }

        const uint32_t sK = sb + AT_QB + (uint32_t)st * AT_STB;
        const uint32_t sV = sK + AT_KB;

        float s[8][4];
        #pragma unroll
        for (int nt = 0; nt < 8; nt++)
            #pragma unroll
            for (int r = 0; r < 4; r++) s[nt][r] = 0.f;

        #pragma unroll
        for (int ks = 0; ks < 4; ++ks) {
            uint32_t kb[8][2];
            #pragma unroll
            for (int nt16 = 0; nt16 < 4; nt16++) {
                const uint32_t bo = sK + ((bRowB + nt16 * 16) * 144 + (uint32_t)(ks * 16) * 2 + bColB * 2);
                LDSM4(kb[nt16*2][0], kb[nt16*2][1], kb[nt16*2+1][0], kb[nt16*2+1][1], bo);
            }
            #pragma unroll
            for (int nt = 0; nt < 8; nt++)
                MMAF16(s[nt], qa[ks], kb[nt][0], kb[nt][1]);
        }

        if (jt * 64 + 63 > qbase + warp * 16) {
            const int colb = jt * 64 + 2 * (lane & 3);
            #pragma unroll
            for (int nt = 0; nt < 8; nt++) {
                const int c0 = colb + nt * 8, c1 = c0 + 1;
                if (c0 > growA)     s[nt][0] = -1e30f;
                if (c1 > growA)     s[nt][1] = -1e30f;
                if (c0 > growA + 8) s[nt][2] = -1e30f;
                if (c1 > growA + 8) s[nt][3] = -1e30f;
            }
        }

        float mx0 = -1e30f, mx1 = -1e30f;
        #pragma unroll
        for (int nt = 0; nt < 8; nt++) {
            mx0 = fmaxf(mx0, fmaxf(s[nt][0], s[nt][1]));
            mx1 = fmaxf(mx1, fmaxf(s[nt][2], s[nt][3]));
        }
        #pragma unroll
        for (int off = 1; off <= 2; off <<= 1) {
            mx0 = fmaxf(mx0, __shfl_xor_sync(0xffffffffu, mx0, off, 4));
            mx1 = fmaxf(mx1, __shfl_xor_sync(0xffffffffu, mx1, off, 4));
        }
        const float mn0 = fmaxf(m0, mx0), mn1 = fmaxf(m1, mx1);
        const float al0 = exp2f((m0 - mn0) * 1.44269504f);
        const float al1 = exp2f((m1 - mn1) * 1.44269504f);
        m0 = mn0; m1 = mn1;
        float ps0 = 0.f, ps1 = 0.f;
        #pragma unroll
        for (int nt = 0; nt < 8; nt++) {
            s[nt][0] = exp2f((s[nt][0] - mn0) * 1.44269504f);
            s[nt][1] = exp2f((s[nt][1] - mn0) * 1.44269504f);
            s[nt][2] = exp2f((s[nt][2] - mn1) * 1.44269504f);
            s[nt][3] = exp2f((s[nt][3] - mn1) * 1.44269504f);
            ps0 += s[nt][0] + s[nt][1];
            ps1 += s[nt][2] + s[nt][3];
        }
        #pragma unroll
        for (int off = 1; off <= 2; off <<= 1) {
            ps0 += __shfl_xor_sync(0xffffffffu, ps0, off, 4);
            ps1 += __shfl_xor_sync(0xffffffffu, ps1, off, 4);
        }
        l0 = l0 * al0 + ps0;
        l1 = l1 * al1 + ps1;
        #pragma unroll
        for (int nt = 0; nt < 8; nt++) {
            o[nt][0] *= al0; o[nt][1] *= al0;
            o[nt][2] *= al1; o[nt][3] *= al1;
        }

        uint32_t pa[4][4];
        #pragma unroll
        for (int j = 0; j < 4; j++) {
            pa[j][0] = pack_h2(s[2*j][0],   s[2*j][1]);
            pa[j][1] = pack_h2(s[2*j][2],   s[2*j][3]);
            pa[j][2] = pack_h2(s[2*j+1][0], s[2*j+1][1]);
            pa[j][3] = pack_h2(s[2*j+1][2], s[2*j+1][3]);
        }

        #pragma unroll
        for (int ks = 0; ks < 4; ++ks) {
            #pragma unroll
            for (int ntp = 0; ntp < 4; ntp++) {
                uint32_t v0, v1, v2, v3;
                const uint32_t vo = sV + ((vRow + ks * 16) * 144 + (vCol + ntp * 16) * 2);
                LDSM4T(v0, v1, v2, v3, vo);
                MMAF16(o[ntp*2],     pa[ks], v0, v1);
                MMAF16(o[ntp*2+1],   pa[ks], v2, v3);
            }
        }

        __syncthreads();
        if (jt + 2 <= jtmax) cpKV(jt + 2, st);
    }

    const float inv0 = 1.0f / l0, inv1 = 1.0f / l1;
    const size_t row0 = tokQ + warp * 16 + rloc0;
    const int colb = hoff + 2 * (lane & 3);
    #pragma unroll
    for (int nt = 0; nt < 8; nt++) {
        *(__half2*)(Og + row0 * TB_D + colb + nt * 8) =
            __floats2half2_rn(o[nt][0] * inv0, o[nt][1] * inv0);
        *(__half2*)(Og + (row0 + 8) * TB_D + colb + nt * 8) =
            __floats2half2_rn(o[nt][2] * inv1, o[nt][3] * inv1);
    }
}

// ---------------- launch ----------------
extern "C" void kernel_launch(void* const* d_in, const int* in_sizes, int n_in,
                              void* d_out, int out_size)
{
    const float* x  = (const float*)d_in[0];
    const float* wq = (const float*)d_in[1];
    const float* wk = (const float*)d_in[2];
    const float* wv = (const float*)d_in[3];
    const float* wo = (const float*)d_in[4];
    const float* w1 = (const float*)d_in[5];
    const float* w2 = (const float*)d_in[6];
    const float* g1 = (const float*)d_in[7];
    const float* g2 = (const float*)d_in[8];
    float* out = (float*)d_out;

    float *x2;
    __half *h16, *q16, *k16, *v16, *o16, *h216, *mid16;
    __half *wq16, *wk16, *wv16, *wo16, *w116, *w216;
    cudaGetSymbolAddress((void**)&x2,    g_x2);
    cudaGetSymbolAddress((void**)&h16,   g_h16);
    cudaGetSymbolAddress((void**)&q16,   g_q16);
    cudaGetSymbolAddress((void**)&k16,   g_k16);
    cudaGetSymbolAddress((void**)&v16,   g_v16);
    cudaGetSymbolAddress((void**)&o16,   g_o16);
    cudaGetSymbolAddress((void**)&h216,  g_h216);
    cudaGetSymbolAddress((void**)&mid16, g_mid16);
    cudaGetSymbolAddress((void**)&wq16,  g_wq16);
    cudaGetSymbolAddress((void**)&wk16,  g_wk16);
    cudaGetSymbolAddress((void**)&wv16,  g_wv16);
    cudaGetSymbolAddress((void**)&wo16,  g_wo16);
    cudaGetSymbolAddress((void**)&w116,  g_w116);
    cudaGetSymbolAddress((void**)&w216,  g_w216);

    cudaFuncSetAttribute(gemm_qkv_k,     cudaFuncAttributeMaxDynamicSharedMemorySize, GEMM_SMEM);
    cudaFuncSetAttribute(gemm_res_k,     cudaFuncAttributeMaxDynamicSharedMemorySize, GEMM_SMEM);
    cudaFuncSetAttribute(gemm_gelu256_k, cudaFuncAttributeMaxDynamicSharedMemorySize, SMEM256);
    cudaFuncSetAttribute(attn_kernel,    cudaFuncAttributeMaxDynamicSharedMemorySize, AT_SMEM);

    // 1: attention-weight converts
    conv4_kernel<<<4096, 256>>>(wq, wq16, wk, wk16, wv, wv16, wo, wo16);
    // 2: FFN-weight converts
    convFF_kernel<<<8192, 256>>>(w1, w116, w2, w216);
    // 3: h = rmsnorm(x, g1) -> fp16
    rmsnorm_h_kernel<<<TB_M, 256>>>(x, g1, h16);
    // 4: q,k,v (fp16, q pre-scaled)
    gemm_qkv_k<<<dim3(TB_D / 128, TB_M / 128, 3), 256, GEMM_SMEM>>>(
        h16, wq16, wk16, wv16, q16, k16, v16);
    // 5: attention -> o fp16   (1 CTA/SM — no register cap, no spills)
    attn_kernel<<<dim3(TB_S / 128, TB_H, TB_B), 256, AT_SMEM>>>(q16, k16, v16, o16);
    // 6: x2 = o @ wo^T + x   <-- ncu -s 5 -c 1 captures this launch
    gemm_res_k<<<dim3(TB_D / 128, TB_M / 128), 256, GEMM_SMEM>>>(
        o16, wo16, x, x2, TB_D, TB_D);
    // 7: h2 = rmsnorm(x2, g2) -> fp16
    rmsnorm_h_kernel<<<TB_M, 256>>>(x2, g2, h216);
    // 8: mid = gelu(h2 @ w1^T) -> fp16  (128x256 tile, ratio 4:1)
    gemm_gelu256_k<<<dim3(TB_FF / 256, TB_M / 128), 256, SMEM256>>>(
        h216, w116, mid16, TB_FF, TB_D);
    // 9: out = mid @ w2^T + x2
    gemm_res_k<<<dim3(TB_D / 128, TB_M / 128), 256, GEMM_SMEM>>>(
        mid16, w216, x2, out, TB_D, TB_FF);
}

// round 15
// speedup vs baseline: 1.1301x; 1.0569x over previous
#include <cuda_runtime.h>
#include <cuda_fp16.h>
#include <math.h>
#include <stdint.h>

#define TB_B  2
#define TB_S  2048
#define TB_D  1024
#define TB_H  16
#define TB_DH 64
#define TB_FF 4096
#define TB_M  4096

// ---------------- scratch (no allocations allowed) ----------------
static __device__ float  g_x2[TB_M * TB_D];
static __device__ __half g_h16 [TB_M * TB_D];
static __device__ __half g_q16 [TB_M * TB_D];
static __device__ __half g_k16 [TB_M * TB_D];
static __device__ __half g_v16 [TB_M * TB_D];
static __device__ __half g_o16 [TB_M * TB_D];
static __device__ __half g_h216[TB_M * TB_D];
static __device__ __half g_mid16[(size_t)TB_M * TB_FF];
static __device__ __half g_wq16[TB_D * TB_D];
static __device__ __half g_wk16[TB_D * TB_D];
static __device__ __half g_wv16[TB_D * TB_D];
static __device__ __half g_wo16[TB_D * TB_D];
static __device__ __half g_w116[TB_FF * TB_D];
static __device__ __half g_w216[TB_D * TB_FF];

// ---------------- helpers ----------------
static __device__ __forceinline__ uint32_t smem_u32(const void* p) {
    uint32_t a;
    asm("{ .reg .u64 t; cvta.to.shared.u64 t, %1; cvt.u32.u64 %0, t; }" : "=r"(a) : "l"(p));
    return a;
}
static __device__ __forceinline__ void cp16(uint32_t d, const void* s) {
    asm volatile("cp.async.cg.shared.global [%0], [%1], 16;" :: "r"(d), "l"(s) : "memory");
}
#define CP_COMMIT()  asm volatile("cp.async.commit_group;" ::: "memory")
#define CP_WAIT(n)   asm volatile("cp.async.wait_group %0;" :: "n"(n) : "memory")

#define LDSM4(r0, r1, r2, r3, addr) \
    asm volatile("ldmatrix.sync.aligned.m8n8.x4.shared.b16 {%0,%1,%2,%3}, [%4];" \
                 : "=r"(r0), "=r"(r1), "=r"(r2), "=r"(r3) : "r"(addr))

#define LDSM4T(r0, r1, r2, r3, addr) \
    asm volatile("ldmatrix.sync.aligned.m8n8.x4.trans.shared.b16 {%0,%1,%2,%3}, [%4];" \
                 : "=r"(r0), "=r"(r1), "=r"(r2), "=r"(r3) : "r"(addr))

#define MMAF16(d, a, b0v, b1v) \
    asm volatile("mma.sync.aligned.m16n8k16.row.col.f32.f16.f16.f32 " \
                 "{%0,%1,%2,%3}, {%4,%5,%6,%7}, {%8,%9}, {%0,%1,%2,%3};" \
                 : "+f"((d)[0]), "+f"((d)[1]), "+f"((d)[2]), "+f"((d)[3]) \
                 : "r"((a)[0]), "r"((a)[1]), "r"((a)[2]), "r"((a)[3]), \
                   "r"(b0v), "r"(b1v))

static __device__ __forceinline__ float gelu_f(float x) {
    return 0.5f * x * (1.0f + erff(x * 0.70710678118654752440f));
}
static __device__ __forceinline__ uint32_t pack_h2(float a, float b) {
    __half2 h = __floats2half2_rn(a, b);
    return *(uint32_t*)&h;
}

// ---------------- merged weight convert kernel (fp32 -> fp16) ----------------
static __device__ __forceinline__ void conv_one(
    const float* __restrict__ s, __half* __restrict__ d, size_t i)
{
    const float4 v = ((const float4*)s)[i];
    ((__half2*)d)[i * 2]     = __floats2half2_rn(v.x, v.y);
    ((__half2*)d)[i * 2 + 1] = __floats2half2_rn(v.z, v.w);
}

// blocks 0..4095: wq,wk,wv,wo (1024 each); 4096..8191: w1; 8192..12287: w2
__global__ void __launch_bounds__(256) conv_all_kernel(
    const float* wq, __half* wq16, const float* wk, __half* wk16,
    const float* wv, __half* wv16, const float* wo, __half* wo16,
    const float* w1, __half* w116, const float* w2, __half* w216)
{
    const int blk = blockIdx.x;
    if (blk < 4096) {
        const int which = blk >> 10;
        const size_t i  = (size_t)(blk & 1023) * 256 + threadIdx.x;
        if (which == 0)      conv_one(wq, wq16, i);
        else if (which == 1) conv_one(wk, wk16, i);
        else if (which == 2) conv_one(wv, wv16, i);
        else                 conv_one(wo, wo16, i);
    } else if (blk < 8192) {
        const size_t i = (size_t)(blk - 4096) * 256 + threadIdx.x;
        conv_one(w1, w116, i);
    } else {
        const size_t i = (size_t)(blk - 8192) * 256 + threadIdx.x;
        conv_one(w2, w216, i);
    }
}

// ---------------- rmsnorm -> fp16 ----------------
__global__ void __launch_bounds__(256) rmsnorm_h_kernel(
    const float* __restrict__ x, const float* __restrict__ g, __half* __restrict__ oh)
{
    const int row = blockIdx.x;
    const int tid = threadIdx.x;
    const float4 xv = ((const float4*)(x + (size_t)row * TB_D))[tid];
    float ss = xv.x * xv.x + xv.y * xv.y + xv.z * xv.z + xv.w * xv.w;
    #pragma unroll
    for (int off = 16; off; off >>= 1)
        ss += __shfl_xor_sync(0xffffffffu, ss, off);
    __shared__ float ws[8];
    __shared__ float s_scale;
    const int wid = tid >> 5, lane = tid & 31;
    if (lane == 0) ws[wid] = ss;
    __syncthreads();
    if (tid == 0) {
        float t = 0.f;
        #pragma unroll
        for (int i = 0; i < 8; i++) t += ws[i];
        s_scale = rsqrtf(t * (1.0f / (float)TB_D) + 1e-5f);
    }
    __syncthreads();
    const float sc = s_scale;
    const float4 gv = ((const float4*)g)[tid];
    const size_t o = (size_t)row * TB_D + tid * 4;
    *(__half2*)(oh + o)     = __floats2half2_rn(xv.x * gv.x * sc, xv.y * gv.y * sc);
    *(__half2*)(oh + o + 2) = __floats2half2_rn(xv.z * gv.z * sc, xv.w * gv.w * sc);
}

// ---------------- fp16 GEMM, 128x128 tile, 256 threads (R10 core) ----------------
#define ARR_BYTES   (128 * 144)
#define STAGE_BYTES (2 * ARR_BYTES)             // 36864 (A + B)
#define N_STAGES    3
#define GEMM_SMEM   (N_STAGES * STAGE_BYTES)    // 110592

template<int EPI>   // 1=gelu->fp16, 2=+res fp32, 3=fp16 scaled
static __device__ __forceinline__ void tc_gemm_core(
    const __half* __restrict__ A, const __half* __restrict__ B,
    const float* __restrict__ res, float* __restrict__ Cf,
    __half* __restrict__ Ch, float oscale,
    int N, int K)
{
    extern __shared__ char smc[];
    const uint32_t sb  = smem_u32(smc);
    const int tid  = threadIdx.x;
    const int lane = tid & 31;
    const int wm   = (tid >> 5) >> 2;     // 0..1
    const int wn   = (tid >> 5) & 3;      // 0..3
    const int bm   = blockIdx.y * 128;
    const int bn   = blockIdx.x * 128;
    const int nch  = K >> 6;

    auto load_chunk = [&](int kc, int st) {
        const uint32_t db  = sb + (uint32_t)st * STAGE_BYTES;
        const int kof = kc * 64;
        #pragma unroll
        for (int it = 0; it < 4; ++it) {
            const int g  = tid + it * 256;
            const int r  = g >> 3, gc = g & 7;
            const uint32_t off = (uint32_t)(r * 144 + gc * 16);
            cp16(db + off,             A + (size_t)(bm + r) * K + kof + gc * 8);
            cp16(db + ARR_BYTES + off, B + (size_t)(bn + r) * K + kof + gc * 8);
        }
        CP_COMMIT();
    };

    float acc[4][4][4];
    #pragma unroll
    for (int mi = 0; mi < 4; mi++)
        #pragma unroll
        for (int ni = 0; ni < 4; ni++)
            #pragma unroll
            for (int r = 0; r < 4; r++) acc[mi][ni][r] = 0.f;

    load_chunk(0, 0);
    if (nch > 1) load_chunk(1, 1);
    if (nch > 2) load_chunk(2, 2);

    const uint32_t aRow = (uint32_t)(wm * 64 + (lane & 15));
    const uint32_t aCol = (uint32_t)((lane >> 4) * 8);
    const int grp = lane >> 3, r8 = lane & 7;
    const uint32_t bRow = (uint32_t)(wn * 32 + (grp >> 1) * 8 + r8);
    const uint32_t bCol = (uint32_t)((grp & 1) * 8);

    for (int i = 0; i < nch; ++i) {
        const int p = i % N_STAGES;
        if (i + 2 < nch)      CP_WAIT(2);
        else if (i + 1 < nch) CP_WAIT(1);
        else                  CP_WAIT(0);
        __syncthreads();

        const uint32_t dA = sb + (uint32_t)p * STAGE_BYTES;
        const uint32_t dB = dA + ARR_BYTES;

        #pragma unroll
        for (int ks = 0; ks < 4; ++ks) {
            uint32_t a[4][4], b[4][2];
            const uint32_t kc2 = (uint32_t)(ks * 16) * 2;
            #pragma unroll
            for (int mi = 0; mi < 4; mi++) {
                const uint32_t ao = (aRow + mi * 16) * 144 + kc2 + aCol * 2;
                LDSM4(a[mi][0], a[mi][1], a[mi][2], a[mi][3], dA + ao);
            }
            #pragma unroll
            for (int nj = 0; nj < 2; nj++) {
                const uint32_t bo = (bRow + nj * 16) * 144 + kc2 + bCol * 2;
                LDSM4(b[nj*2][0], b[nj*2][1], b[nj*2+1][0], b[nj*2+1][1], dB + bo);
            }
            #pragma unroll
            for (int mi = 0; mi < 4; mi++)
                #pragma unroll
                for (int ni = 0; ni < 4; ni++)
                    MMAF16(acc[mi][ni], a[mi], b[ni][0], b[ni][1]);
        }
        __syncthreads();
        if (i + N_STAGES < nch) load_chunk(i + N_STAGES, p);
    }

    const int rq = lane >> 2, cq = (lane & 3) * 2;
    #pragma unroll
    for (int mi = 0; mi < 4; mi++) {
        #pragma unroll
        for (int ni = 0; ni < 4; ni++) {
            const int row0 = bm + wm * 64 + mi * 16 + rq;
            const int col  = bn + wn * 32 + ni * 8 + cq;
            #pragma unroll
            for (int half = 0; half < 2; half++) {
                const int row = row0 + half * 8;
                const size_t go = (size_t)row * N + col;
                const float v0 = acc[mi][ni][half * 2 + 0];
                const float v1 = acc[mi][ni][half * 2 + 1];
                if (EPI == 2) {
                    const float2 rv = *(const float2*)(res + go);
                    float2 v; v.x = v0 + rv.x; v.y = v1 + rv.y;
                    *(float2*)(Cf + go) = v;
                } else if (EPI == 3) {
                    *(__half2*)(Ch + go) = __floats2half2_rn(v0 * oscale, v1 * oscale);
                } else {
                    *(__half2*)(Ch + go) = __floats2half2_rn(gelu_f(v0), gelu_f(v1));
                }
            }
        }
    }
}

__global__ void __launch_bounds__(256, 2) gemm_qkv_k(
    const __half* A,
    const __half* wq, const __half* wk, const __half* wv,
    __half* q, __half* k, __half* v)
{
    const __half* B; __half* C; float sc;
    if (blockIdx.z == 0)      { B = wq; C = q; sc = 0.125f; }
    else if (blockIdx.z == 1) { B = wk; C = k; sc = 1.0f; }
    else                      { B = wv; C = v; sc = 1.0f; }
    tc_gemm_core<3>(A, B, nullptr, nullptr, C, sc, TB_D, TB_D);
}
__global__ void __launch_bounds__(256, 2) gemm_res_k(
    const __half* A, const __half* B,
    const float* res, float* C, int N, int K)
{
    tc_gemm_core<2>(A, B, res, C, nullptr, 1.f, N, K);
}
__global__ void __launch_bounds__(256, 2) gemm_gelu_k(
    const __half* A, const __half* B, __half* C, int N, int K)
{
    tc_gemm_core<1>(A, B, nullptr, nullptr, C, 1.f, N, K);
}

// ---------------- fp16 tensor-core causal flash attention ----------------
#define AT_LD    72
#define AT_QB    (128 * AT_LD * 2)
#define AT_KB    (64 * AT_LD * 2)
#define AT_STB   (2 * AT_KB)
#define AT_SMEM  (AT_QB + 2 * AT_STB)

__global__ void __launch_bounds__(256, 1) attn_kernel(
    const __half* __restrict__ Qg, const __half* __restrict__ Kg,
    const __half* __restrict__ Vg, __half* __restrict__ Og)
{
    extern __shared__ char smc[];
    const uint32_t sb = smem_u32(smc);
    const uint32_t sQ = sb;

    const int qt   = gridDim.x - 1 - blockIdx.x;
    const int h    = blockIdx.y;
    const int b    = blockIdx.z;
    const int tid  = threadIdx.x;
    const int lane = tid & 31;
    const int warp = tid >> 5;

    const int qbase   = qt * 128;
    const size_t tokQ = (size_t)b * TB_S + qbase;
    const size_t tokK = (size_t)b * TB_S;
    const int hoff    = h * TB_DH;
    const int jtmax   = 2 * qt + 1;

    auto cpQ = [&]() {
        #pragma unroll
        for (int it = 0; it < 4; ++it) {
            const int g = tid + it * 256;
            const int r = g >> 3, c = g & 7;
            cp16(sQ + (uint32_t)(r * 144 + c * 16),
                 Qg + (tokQ + r) * TB_D + hoff + c * 8);
        }
        CP_COMMIT();
    };
    auto cpKV = [&](int jt, int st) {
        const uint32_t sK = sb + AT_QB + (uint32_t)st * AT_STB;
        const uint32_t sV = sK + AT_KB;
        const size_t rowb = tokK + (size_t)jt * 64;
        #pragma unroll
        for (int it = 0; it < 2; ++it) {
            const int g = tid + it * 256;
            const int r = g >> 3, c = g & 7;
            const uint32_t off = (uint32_t)(r * 144 + c * 16);
            const size_t so = (rowb + r) * TB_D + hoff + c * 8;
            cp16(sK + off, Kg + so);
            cp16(sV + off, Vg + so);
        }
        CP_COMMIT();
    };

    cpQ();
    cpKV(0, 0);
    cpKV(1, 1);

    const uint32_t aRow = (uint32_t)(warp * 16 + (lane & 15));
    const uint32_t aCol = (uint32_t)((lane >> 4) * 8);
    const int grp = lane >> 3, r8 = lane & 7;
    const uint32_t bRowB = (uint32_t)((grp >> 1) * 8 + r8);
    const uint32_t bColB = (uint32_t)((grp & 1) * 8);
    const uint32_t vRow = (uint32_t)(lane & 15);
    const uint32_t vCol = (uint32_t)((lane >> 4) * 8);

    uint32_t qa[4][4];
    float o[8][4];
    #pragma unroll
    for (int nt = 0; nt < 8; nt++)
        #pragma unroll
        for (int r = 0; r < 4; r++) o[nt][r] = 0.f;
    float m0 = -1e30f, m1 = -1e30f, l0 = 0.f, l1 = 0.f;

    const int rloc0 = lane >> 2;
    const int growA = qbase + warp * 16 + rloc0;

    for (int jt = 0; jt <= jtmax; ++jt) {
        const int st = jt & 1;
        if (jt + 1 <= jtmax) CP_WAIT(1); else CP_WAIT(0);
        __syncthreads();

        if (jt == 0) {
            #pragma unroll
            for (int ks = 0; ks < 4; ++ks) {
                const uint32_t ao = sQ + (aRow * 144 + (uint32_t)(ks * 16) * 2 + aCol * 2);
                LDSM4(qa[ks][0], qa[ks][1], qa[ks][2], qa[ks][3], ao);
            }
        }

        const uint32_t sK = sb + AT_QB + (uint32_t)st * AT_STB;
        const uint32_t sV = sK + AT_KB;

        float s[8][4];
        #pragma unroll
        for (int nt = 0; nt < 8; nt++)
            #pragma unroll
            for (int r = 0; r < 4; r++) s[nt][r] = 0.f;

        #pragma unroll
        for (int ks = 0; ks < 4; ++ks) {
            uint32_t kb[8][2];
            #pragma unroll
            for (int nt16 = 0; nt16 < 4; nt16++) {
                const uint32_t bo = sK + ((bRowB + nt16 * 16) * 144 + (uint32_t)(ks * 16) * 2 + bColB * 2);
                LDSM4(kb[nt16*2][0], kb[nt16*2][1], kb[nt16*2+1][0], kb[nt16*2+1][1], bo);
            }
            #pragma unroll
            for (int nt = 0; nt < 8; nt++)
                MMAF16(s[nt], qa[ks], kb[nt][0], kb[nt][1]);
        }

        if (jt * 64 + 63 > qbase + warp * 16) {
            const int colb = jt * 64 + 2 * (lane & 3);
            #pragma unroll
            for (int nt = 0; nt < 8; nt++) {
                const int c0 = colb + nt * 8, c1 = c0 + 1;
                if (c0 > growA)     s[nt][0] = -1e30f;
                if (c1 > growA)     s[nt][1] = -1e30f;
                if (c0 > growA + 8) s[nt][2] = -1e30f;
                if (c1 > growA + 8) s[nt][3] = -1e30f;
            }
        }

        float mx0 = -1e30f, mx1 = -1e30f;
        #pragma unroll
        for (int nt = 0; nt < 8; nt++) {
            mx0 = fmaxf(mx0, fmaxf(s[nt][0], s[nt][1]));
            mx1 = fmaxf(mx1, fmaxf(s[nt][2], s[nt][3]));
        }
        #pragma unroll
        for (int off = 1; off <= 2; off <<= 1) {
            mx0 = fmaxf(mx0, __shfl_xor_sync(0xffffffffu, mx0, off, 4));
            mx1 = fmaxf(mx1, __shfl_xor_sync(0xffffffffu, mx1, off, 4));
        }
        const float mn0 = fmaxf(m0, mx0), mn1 = fmaxf(m1, mx1);
        const float al0 = exp2f((m0 - mn0) * 1.44269504f);
        const float al1 = exp2f((m1 - mn1) * 1.44269504f);
        m0 = mn0; m1 = mn1;
        float ps0 = 0.f, ps1 = 0.f;
        #pragma unroll
        for (int nt = 0; nt < 8; nt++) {
            s[nt][0] = exp2f((s[nt][0] - mn0) * 1.44269504f);
            s[nt][1] = exp2f((s[nt][1] - mn0) * 1.44269504f);
            s[nt][2] = exp2f((s[nt][2] - mn1) * 1.44269504f);
            s[nt][3] = exp2f((s[nt][3] - mn1) * 1.44269504f);
            ps0 += s[nt][0] + s[nt][1];
            ps1 += s[nt][2] + s[nt][3];
        }
        #pragma unroll
        for (int off = 1; off <= 2; off <<= 1) {
            ps0 += __shfl_xor_sync(0xffffffffu, ps0, off, 4);
            ps1 += __shfl_xor_sync(0xffffffffu, ps1, off, 4);
        }
        l0 = l0 * al0 + ps0;
        l1 = l1 * al1 + ps1;
        #pragma unroll
        for (int nt = 0; nt < 8; nt++) {
            o[nt][0] *= al0; o[nt][1] *= al0;
            o[nt][2] *= al1; o[nt][3] *= al1;
        }

        uint32_t pa[4][4];
        #pragma unroll
        for (int j = 0; j < 4; j++) {
            pa[j][0] = pack_h2(s[2*j][0],   s[2*j][1]);
            pa[j][1] = pack_h2(s[2*j][2],   s[2*j][3]);
            pa[j][2] = pack_h2(s[2*j+1][0], s[2*j+1][1]);
            pa[j][3] = pack_h2(s[2*j+1][2], s[2*j+1][3]);
        }

        #pragma unroll
        for (int ks = 0; ks < 4; ++ks) {
            #pragma unroll
            for (int ntp = 0; ntp < 4; ntp++) {
                uint32_t v0, v1, v2, v3;
                const uint32_t vo = sV + ((vRow + ks * 16) * 144 + (vCol + ntp * 16) * 2);
                LDSM4T(v0, v1, v2, v3, vo);
                MMAF16(o[ntp*2],     pa[ks], v0, v1);
                MMAF16(o[ntp*2+1],   pa[ks], v2, v3);
            }
        }

        __syncthreads();
        if (jt + 2 <= jtmax) cpKV(jt + 2, st);
    }

    const float inv0 = 1.0f / l0, inv1 = 1.0f / l1;
    const size_t row0 = tokQ + warp * 16 + rloc0;
    const int colb = hoff + 2 * (lane & 3);
    #pragma unroll
    for (int nt = 0; nt < 8; nt++) {
        *(__half2*)(Og + row0 * TB_D + colb + nt * 8) =
            __floats2half2_rn(o[nt][0] * inv0, o[nt][1] * inv0);
        *(__half2*)(Og + (row0 + 8) * TB_D + colb + nt * 8) =
            __floats2half2_rn(o[nt][2] * inv1, o[nt][3] * inv1);
    }
}

// ---------------- launch ----------------
extern "C" void kernel_launch(void* const* d_in, const int* in_sizes, int n_in,
                              void* d_out, int out_size)
{
    const float* x  = (const float*)d_in[0];
    const float* wq = (const float*)d_in[1];
    const float* wk = (const float*)d_in[2];
    const float* wv = (const float*)d_in[3];
    const float* wo = (const float*)d_in[4];
    const float* w1 = (const float*)d_in[5];
    const float* w2 = (const float*)d_in[6];
    const float* g1 = (const float*)d_in[7];
    const float* g2 = (const float*)d_in[8];
    float* out = (float*)d_out;

    float *x2;
    __half *h16, *q16, *k16, *v16, *o16, *h216, *mid16;
    __half *wq16, *wk16, *wv16, *wo16, *w116, *w216;
    cudaGetSymbolAddress((void**)&x2,    g_x2);
    cudaGetSymbolAddress((void**)&h16,   g_h16);
    cudaGetSymbolAddress((void**)&q16,   g_q16);
    cudaGetSymbolAddress((void**)&k16,   g_k16);
    cudaGetSymbolAddress((void**)&v16,   g_v16);
    cudaGetSymbolAddress((void**)&o16,   g_o16);
    cudaGetSymbolAddress((void**)&h216,  g_h216);
    cudaGetSymbolAddress((void**)&mid16, g_mid16);
    cudaGetSymbolAddress((void**)&wq16,  g_wq16);
    cudaGetSymbolAddress((void**)&wk16,  g_wk16);
    cudaGetSymbolAddress((void**)&wv16,  g_wv16);
    cudaGetSymbolAddress((void**)&wo16,  g_wo16);
    cudaGetSymbolAddress((void**)&w116,  g_w116);
    cudaGetSymbolAddress((void**)&w216,  g_w216);

    cudaFuncSetAttribute(gemm_qkv_k,  cudaFuncAttributeMaxDynamicSharedMemorySize, GEMM_SMEM);
    cudaFuncSetAttribute(gemm_res_k,  cudaFuncAttributeMaxDynamicSharedMemorySize, GEMM_SMEM);
    cudaFuncSetAttribute(gemm_gelu_k, cudaFuncAttributeMaxDynamicSharedMemorySize, GEMM_SMEM);
    cudaFuncSetAttribute(attn_kernel, cudaFuncAttributeMaxDynamicSharedMemorySize, AT_SMEM);

    // 1: all weight converts (single launch)
    conv_all_kernel<<<12288, 256>>>(wq, wq16, wk, wk16, wv, wv16, wo, wo16,
                                    w1, w116, w2, w216);
    // 2: h = rmsnorm(x, g1) -> fp16
    rmsnorm_h_kernel<<<TB_M, 256>>>(x, g1, h16);
    // 3: q,k,v (fp16, q pre-scaled)
    gemm_qkv_k<<<dim3(TB_D / 128, TB_M / 128, 3), 256, GEMM_SMEM>>>(
        h16, wq16, wk16, wv16, q16, k16, v16);
    // 4: attention -> o fp16
    attn_kernel<<<dim3(TB_S / 128, TB_H, TB_B), 256, AT_SMEM>>>(q16, k16, v16, o16);
    // 5: x2 = o @ wo^T + x
    gemm_res_k<<<dim3(TB_D / 128, TB_M / 128), 256, GEMM_SMEM>>>(
        o16, wo16, x, x2, TB_D, TB_D);
    // 6: h2 = rmsnorm(x2, g2) -> fp16
    rmsnorm_h_kernel<<<TB_M, 256>>>(x2, g2, h216);
    // 7: mid = gelu(h2 @ w1^T) -> fp16  (128x128 R10 core)
    gemm_gelu_k<<<dim3(TB_FF / 128, TB_M / 128), 256, GEMM_SMEM>>>(
        h216, w116, mid16, TB_FF, TB_D);
    // 8: out = mid @ w2^T + x2
    gemm_res_k<<<dim3(TB_D / 128, TB_M / 128), 256, GEMM_SMEM>>>(
        mid16, w216, x2, out, TB_D, TB_FF);
}

// round 16
// speedup vs baseline: 1.1450x; 1.0132x over previous
#include <cuda_runtime.h>
#include <cuda_fp16.h>
#include <math.h>
#include <stdint.h>

#define TB_B  2
#define TB_S  2048
#define TB_D  1024
#define TB_H  16
#define TB_DH 64
#define TB_FF 4096
#define TB_M  4096

// ---------------- scratch (no allocations allowed) ----------------
static __device__ float  g_x2[TB_M * TB_D];
static __device__ __half g_h16 [TB_M * TB_D];
static __device__ __half g_q16 [TB_M * TB_D];
static __device__ __half g_k16 [TB_M * TB_D];
static __device__ __half g_v16 [TB_M * TB_D];
static __device__ __half g_o16 [TB_M * TB_D];
static __device__ __half g_h216[TB_M * TB_D];
static __device__ __half g_mid16[(size_t)TB_M * TB_FF];
static __device__ __half g_wq16[TB_D * TB_D];
static __device__ __half g_wk16[TB_D * TB_D];
static __device__ __half g_wv16[TB_D * TB_D];
static __device__ __half g_wo16[TB_D * TB_D];
static __device__ __half g_w116[TB_FF * TB_D];
static __device__ __half g_w216[TB_D * TB_FF];

// ---------------- helpers ----------------
static __device__ __forceinline__ uint32_t smem_u32(const void* p) {
    uint32_t a;
    asm("{ .reg .u64 t; cvta.to.shared.u64 t, %1; cvt.u32.u64 %0, t; }" : "=r"(a) : "l"(p));
    return a;
}
static __device__ __forceinline__ void cp16(uint32_t d, const void* s) {
    asm volatile("cp.async.cg.shared.global [%0], [%1], 16;" :: "r"(d), "l"(s) : "memory");
}
#define CP_COMMIT()  asm volatile("cp.async.commit_group;" ::: "memory")
#define CP_WAIT(n)   asm volatile("cp.async.wait_group %0;" :: "n"(n) : "memory")

#define LDSM4(r0, r1, r2, r3, addr) \
    asm volatile("ldmatrix.sync.aligned.m8n8.x4.shared.b16 {%0,%1,%2,%3}, [%4];" \
                 : "=r"(r0), "=r"(r1), "=r"(r2), "=r"(r3) : "r"(addr))

#define LDSM4T(r0, r1, r2, r3, addr) \
    asm volatile("ldmatrix.sync.aligned.m8n8.x4.trans.shared.b16 {%0,%1,%2,%3}, [%4];" \
                 : "=r"(r0), "=r"(r1), "=r"(r2), "=r"(r3) : "r"(addr))

#define MMAF16(d, a, b0v, b1v) \
    asm volatile("mma.sync.aligned.m16n8k16.row.col.f32.f16.f16.f32 " \
                 "{%0,%1,%2,%3}, {%4,%5,%6,%7}, {%8,%9}, {%0,%1,%2,%3};" \
                 : "+f"((d)[0]), "+f"((d)[1]), "+f"((d)[2]), "+f"((d)[3]) \
                 : "r"((a)[0]), "r"((a)[1]), "r"((a)[2]), "r"((a)[3]), \
                   "r"(b0v), "r"(b1v))

#define H2EX2(out, in) \
    asm("ex2.approx.f16x2 %0, %1;" : "=r"(out) : "r"(in))

static __device__ __forceinline__ float gelu_f(float x) {
    return 0.5f * x * (1.0f + erff(x * 0.70710678118654752440f));
}
static __device__ __forceinline__ uint32_t pack_h2f(float a, float b) {
    __half2 h = __floats2half2_rn(a, b);
    return *(uint32_t*)&h;
}

// ---------------- merged weight convert kernel (fp32 -> fp16) ----------------
static __device__ __forceinline__ void conv_one(
    const float* __restrict__ s, __half* __restrict__ d, size_t i)
{
    const float4 v = ((const float4*)s)[i];
    ((__half2*)d)[i * 2]     = __floats2half2_rn(v.x, v.y);
    ((__half2*)d)[i * 2 + 1] = __floats2half2_rn(v.z, v.w);
}

__global__ void __launch_bounds__(256) conv_all_kernel(
    const float* wq, __half* wq16, const float* wk, __half* wk16,
    const float* wv, __half* wv16, const float* wo, __half* wo16,
    const float* w1, __half* w116, const float* w2, __half* w216)
{
    const int blk = blockIdx.x;
    if (blk < 4096) {
        const int which = blk >> 10;
        const size_t i  = (size_t)(blk & 1023) * 256 + threadIdx.x;
        if (which == 0)      conv_one(wq, wq16, i);
        else if (which == 1) conv_one(wk, wk16, i);
        else if (which == 2) conv_one(wv, wv16, i);
        else                 conv_one(wo, wo16, i);
    } else if (blk < 8192) {
        const size_t i = (size_t)(blk - 4096) * 256 + threadIdx.x;
        conv_one(w1, w116, i);
    } else {
        const size_t i = (size_t)(blk - 8192) * 256 + threadIdx.x;
        conv_one(w2, w216, i);
    }
}

// ---------------- rmsnorm -> fp16 ----------------
__global__ void __launch_bounds__(256) rmsnorm_h_kernel(
    const float* __restrict__ x, const float* __restrict__ g, __half* __restrict__ oh)
{
    const int row = blockIdx.x;
    const int tid = threadIdx.x;
    const float4 xv = ((const float4*)(x + (size_t)row * TB_D))[tid];
    float ss = xv.x * xv.x + xv.y * xv.y + xv.z * xv.z + xv.w * xv.w;
    #pragma unroll
    for (int off = 16; off; off >>= 1)
        ss += __shfl_xor_sync(0xffffffffu, ss, off);
    __shared__ float ws[8];
    __shared__ float s_scale;
    const int wid = tid >> 5, lane = tid & 31;
    if (lane == 0) ws[wid] = ss;
    __syncthreads();
    if (tid == 0) {
        float t = 0.f;
        #pragma unroll
        for (int i = 0; i < 8; i++) t += ws[i];
        s_scale = rsqrtf(t * (1.0f / (float)TB_D) + 1e-5f);
    }
    __syncthreads();
    const float sc = s_scale;
    const float4 gv = ((const float4*)g)[tid];
    const size_t o = (size_t)row * TB_D + tid * 4;
    *(__half2*)(oh + o)     = __floats2half2_rn(xv.x * gv.x * sc, xv.y * gv.y * sc);
    *(__half2*)(oh + o + 2) = __floats2half2_rn(xv.z * gv.z * sc, xv.w * gv.w * sc);
}

// ---------------- fp16 GEMM, 128x128 tile, 256 threads (R10 core) ----------------
#define ARR_BYTES   (128 * 144)
#define STAGE_BYTES (2 * ARR_BYTES)
#define N_STAGES    3
#define GEMM_SMEM   (N_STAGES * STAGE_BYTES)

template<int EPI>   // 1=gelu->fp16, 2=+res fp32, 3=fp16 scaled
static __device__ __forceinline__ void tc_gemm_core(
    const __half* __restrict__ A, const __half* __restrict__ B,
    const float* __restrict__ res, float* __restrict__ Cf,
    __half* __restrict__ Ch, float oscale,
    int N, int K)
{
    extern __shared__ char smc[];
    const uint32_t sb  = smem_u32(smc);
    const int tid  = threadIdx.x;
    const int lane = tid & 31;
    const int wm   = (tid >> 5) >> 2;
    const int wn   = (tid >> 5) & 3;
    const int bm   = blockIdx.y * 128;
    const int bn   = blockIdx.x * 128;
    const int nch  = K >> 6;

    auto load_chunk = [&](int kc, int st) {
        const uint32_t db  = sb + (uint32_t)st * STAGE_BYTES;
        const int kof = kc * 64;
        #pragma unroll
        for (int it = 0; it < 4; ++it) {
            const int g  = tid + it * 256;
            const int r  = g >> 3, gc = g & 7;
            const uint32_t off = (uint32_t)(r * 144 + gc * 16);
            cp16(db + off,             A + (size_t)(bm + r) * K + kof + gc * 8);
            cp16(db + ARR_BYTES + off, B + (size_t)(bn + r) * K + kof + gc * 8);
        }
        CP_COMMIT();
    };

    float acc[4][4][4];
    #pragma unroll
    for (int mi = 0; mi < 4; mi++)
        #pragma unroll
        for (int ni = 0; ni < 4; ni++)
            #pragma unroll
            for (int r = 0; r < 4; r++) acc[mi][ni][r] = 0.f;

    load_chunk(0, 0);
    if (nch > 1) load_chunk(1, 1);
    if (nch > 2) load_chunk(2, 2);

    const uint32_t aRow = (uint32_t)(wm * 64 + (lane & 15));
    const uint32_t aCol = (uint32_t)((lane >> 4) * 8);
    const int grp = lane >> 3, r8 = lane & 7;
    const uint32_t bRow = (uint32_t)(wn * 32 + (grp >> 1) * 8 + r8);
    const uint32_t bCol = (uint32_t)((grp & 1) * 8);

    for (int i = 0; i < nch; ++i) {
        const int p = i % N_STAGES;
        if (i + 2 < nch)      CP_WAIT(2);
        else if (i + 1 < nch) CP_WAIT(1);
        else                  CP_WAIT(0);
        __syncthreads();

        const uint32_t dA = sb + (uint32_t)p * STAGE_BYTES;
        const uint32_t dB = dA + ARR_BYTES;

        #pragma unroll
        for (int ks = 0; ks < 4; ++ks) {
            uint32_t a[4][4], b[4][2];
            const uint32_t kc2 = (uint32_t)(ks * 16) * 2;
            #pragma unroll
            for (int mi = 0; mi < 4; mi++) {
                const uint32_t ao = (aRow + mi * 16) * 144 + kc2 + aCol * 2;
                LDSM4(a[mi][0], a[mi][1], a[mi][2], a[mi][3], dA + ao);
            }
            #pragma unroll
            for (int nj = 0; nj < 2; nj++) {
                const uint32_t bo = (bRow + nj * 16) * 144 + kc2 + bCol * 2;
                LDSM4(b[nj*2][0], b[nj*2][1], b[nj*2+1][0], b[nj*2+1][1], dB + bo);
            }
            #pragma unroll
            for (int mi = 0; mi < 4; mi++)
                #pragma unroll
                for (int ni = 0; ni < 4; ni++)
                    MMAF16(acc[mi][ni], a[mi], b[ni][0], b[ni][1]);
        }
        __syncthreads();
        if (i + N_STAGES < nch) load_chunk(i + N_STAGES, p);
    }

    const int rq = lane >> 2, cq = (lane & 3) * 2;
    #pragma unroll
    for (int mi = 0; mi < 4; mi++) {
        #pragma unroll
        for (int ni = 0; ni < 4; ni++) {
            const int row0 = bm + wm * 64 + mi * 16 + rq;
            const int col  = bn + wn * 32 + ni * 8 + cq;
            #pragma unroll
            for (int half = 0; half < 2; half++) {
                const int row = row0 + half * 8;
                const size_t go = (size_t)row * N + col;
                const float v0 = acc[mi][ni][half * 2 + 0];
                const float v1 = acc[mi][ni][half * 2 + 1];
                if (EPI == 2) {
                    const float2 rv = *(const float2*)(res + go);
                    float2 v; v.x = v0 + rv.x; v.y = v1 + rv.y;
                    *(float2*)(Cf + go) = v;
                } else if (EPI == 3) {
                    *(__half2*)(Ch + go) = __floats2half2_rn(v0 * oscale, v1 * oscale);
                } else {
                    *(__half2*)(Ch + go) = __floats2half2_rn(gelu_f(v0), gelu_f(v1));
                }
            }
        }
    }
}

__global__ void __launch_bounds__(256, 2) gemm_qkv_k(
    const __half* A,
    const __half* wq, const __half* wk, const __half* wv,
    __half* q, __half* k, __half* v)
{
    const __half* B; __half* C; float sc;
    // q pre-scaled by 1/sqrt(DH) * log2(e) so attention scores are in log2 units
    if (blockIdx.z == 0)      { B = wq; C = q; sc = 0.125f * 1.44269504f; }
    else if (blockIdx.z == 1) { B = wk; C = k; sc = 1.0f; }
    else                      { B = wv; C = v; sc = 1.0f; }
    tc_gemm_core<3>(A, B, nullptr, nullptr, C, sc, TB_D, TB_D);
}
__global__ void __launch_bounds__(256, 2) gemm_res_k(
    const __half* A, const __half* B,
    const float* res, float* C, int N, int K)
{
    tc_gemm_core<2>(A, B, res, C, nullptr, 1.f, N, K);
}
__global__ void __launch_bounds__(256, 2) gemm_gelu_k(
    const __half* A, const __half* B, __half* C, int N, int K)
{
    tc_gemm_core<1>(A, B, nullptr, nullptr, C, 1.f, N, K);
}

// ---------------- fp16 tensor-core causal flash attention, Bc=128 ----------------
// Br=128 (8 warps x 16 rows), Bc=128. Scores arrive in log2 units (q pre-scaled).
#define AT_QB    (128 * 144)            // 18432
#define AT_KB    (128 * 144)            // 18432 per K or V tile
#define AT_STB   (2 * AT_KB)            // 36864 per stage
#define AT_SMEM  (AT_QB + 2 * AT_STB)   // 92160

__global__ void __launch_bounds__(256, 1) attn_kernel(
    const __half* __restrict__ Qg, const __half* __restrict__ Kg,
    const __half* __restrict__ Vg, __half* __restrict__ Og)
{
    extern __shared__ char smc[];
    const uint32_t sb = smem_u32(smc);
    const uint32_t sQ = sb;

    const int qt   = gridDim.x - 1 - blockIdx.x;   // big tiles first
    const int h    = blockIdx.y;
    const int b    = blockIdx.z;
    const int tid  = threadIdx.x;
    const int lane = tid & 31;
    const int warp = tid >> 5;

    const int qbase   = qt * 128;
    const size_t tokQ = (size_t)b * TB_S + qbase;
    const size_t tokK = (size_t)b * TB_S;
    const int hoff    = h * TB_DH;
    const int jtmax   = qt;                         // 128-wide KV tiles

    auto cpQ = [&]() {
        #pragma unroll
        for (int it = 0; it < 4; ++it) {
            const int g = tid + it * 256;
            const int r = g >> 3, c = g & 7;
            cp16(sQ + (uint32_t)(r * 144 + c * 16),
                 Qg + (tokQ + r) * TB_D + hoff + c * 8);
        }
        CP_COMMIT();
    };
    auto cpKV = [&](int jt, int st) {
        const uint32_t sK = sb + AT_QB + (uint32_t)st * AT_STB;
        const uint32_t sV = sK + AT_KB;
        const size_t rowb = tokK + (size_t)jt * 128;
        #pragma unroll
        for (int it = 0; it < 4; ++it) {
            const int g = tid + it * 256;
            const int r = g >> 3, c = g & 7;
            const uint32_t off = (uint32_t)(r * 144 + c * 16);
            const size_t so = (rowb + r) * TB_D + hoff + c * 8;
            cp16(sK + off, Kg + so);
            cp16(sV + off, Vg + so);
        }
        CP_COMMIT();
    };

    cpQ();
    cpKV(0, 0);
    if (jtmax >= 1) cpKV(1, 1);

    const uint32_t aRow = (uint32_t)(warp * 16 + (lane & 15));
    const uint32_t aCol = (uint32_t)((lane >> 4) * 8);
    const int grp = lane >> 3, r8 = lane & 7;
    const uint32_t bRowB = (uint32_t)((grp >> 1) * 8 + r8);
    const uint32_t bColB = (uint32_t)((grp & 1) * 8);
    const uint32_t vRow = (uint32_t)(lane & 15);
    const uint32_t vCol = (uint32_t)((lane >> 4) * 8);

    uint32_t qa[4][4];
    float o[8][4];
    #pragma unroll
    for (int nt = 0; nt < 8; nt++)
        #pragma unroll
        for (int r = 0; r < 4; r++) o[nt][r] = 0.f;
    float m0 = -1e30f, m1 = -1e30f, l0 = 0.f, l1 = 0.f;

    const int rloc0 = lane >> 2;
    const int growA = qbase + warp * 16 + rloc0;

    for (int jt = 0; jt <= jtmax; ++jt) {
        const int st = jt & 1;
        if (jt + 1 <= jtmax) CP_WAIT(1); else CP_WAIT(0);
        __syncthreads();

        if (jt == 0) {
            #pragma unroll
            for (int ks = 0; ks < 4; ++ks) {
                const uint32_t ao = sQ + (aRow * 144 + (uint32_t)(ks * 16) * 2 + aCol * 2);
                LDSM4(qa[ks][0], qa[ks][1], qa[ks][2], qa[ks][3], ao);
            }
        }

        const uint32_t sK = sb + AT_QB + (uint32_t)st * AT_STB;
        const uint32_t sV = sK + AT_KB;

        // ---- S = q·k^T (log2 units), 16 n-tiles of 8 ----
        float s[16][4];
        #pragma unroll
        for (int nt = 0; nt < 16; nt++)
            #pragma unroll
            for (int r = 0; r < 4; r++) s[nt][r] = 0.f;

        #pragma unroll
        for (int ks = 0; ks < 4; ++ks) {
            uint32_t kb[16][2];
            #pragma unroll
            for (int nt16 = 0; nt16 < 8; nt16++) {
                const uint32_t bo = sK + ((bRowB + nt16 * 16) * 144 + (uint32_t)(ks * 16) * 2 + bColB * 2);
                LDSM4(kb[nt16*2][0], kb[nt16*2][1], kb[nt16*2+1][0], kb[nt16*2+1][1], bo);
            }
            #pragma unroll
            for (int nt = 0; nt < 16; nt++)
                MMAF16(s[nt], qa[ks], kb[nt][0], kb[nt][1]);
        }

        // ---- causal mask (only the diagonal tile) ----
        if (jt == qt) {
            const int colb = jt * 128 + 2 * (lane & 3);
            #pragma unroll
            for (int nt = 0; nt < 16; nt++) {
                const int c0 = colb + nt * 8, c1 = c0 + 1;
                if (c0 > growA)     s[nt][0] = -1e30f;
                if (c1 > growA)     s[nt][1] = -1e30f;
                if (c0 > growA + 8) s[nt][2] = -1e30f;
                if (c1 > growA + 8) s[nt][3] = -1e30f;
            }
        }

        // ---- online softmax (log2 units) ----
        float mx0 = -1e30f, mx1 = -1e30f;
        #pragma unroll
        for (int nt = 0; nt < 16; nt++) {
            mx0 = fmaxf(mx0, fmaxf(s[nt][0], s[nt][1]));
            mx1 = fmaxf(mx1, fmaxf(s[nt][2], s[nt][3]));
        }
        #pragma unroll
        for (int off = 1; off <= 2; off <<= 1) {
            mx0 = fmaxf(mx0, __shfl_xor_sync(0xffffffffu, mx0, off, 4));
            mx1 = fmaxf(mx1, __shfl_xor_sync(0xffffffffu, mx1, off, 4));
        }
        const float mn0 = fmaxf(m0, mx0), mn1 = fmaxf(m1, mx1);
        const float al0 = exp2f(m0 - mn0);
        const float al1 = exp2f(m1 - mn1);
        m0 = mn0; m1 = mn1;

        // exp via ex2.approx.f16x2 -> directly builds fp16 P fragments
        uint32_t pa[8][4];
        float ps0 = 0.f, ps1 = 0.f;
        #pragma unroll
        for (int nt = 0; nt < 16; nt++) {
            uint32_t e01, e23;
            const uint32_t h01 = pack_h2f(s[nt][0] - mn0, s[nt][1] - mn0);
            const uint32_t h23 = pack_h2f(s[nt][2] - mn1, s[nt][3] - mn1);
            H2EX2(e01, h01);
            H2EX2(e23, h23);
            const float2 f01 = __half22float2(*(const __half2*)&e01);
            const float2 f23 = __half22float2(*(const __half2*)&e23);
            ps0 += f01.x + f01.y;
            ps1 += f23.x + f23.y;
            pa[nt >> 1][(nt & 1) * 2]     = e01;
            pa[nt >> 1][(nt & 1) * 2 + 1] = e23;
        }
        #pragma unroll
        for (int off = 1; off <= 2; off <<= 1) {
            ps0 += __shfl_xor_sync(0xffffffffu, ps0, off, 4);
            ps1 += __shfl_xor_sync(0xffffffffu, ps1, off, 4);
        }
        l0 = l0 * al0 + ps0;
        l1 = l1 * al1 + ps1;
        #pragma unroll
        for (int nt = 0; nt < 8; nt++) {
            o[nt][0] *= al0; o[nt][1] *= al0;
            o[nt][2] *= al1; o[nt][3] *= al1;
        }

        // ---- O += P·V (P is 128 wide -> 8 k-steps) ----
        #pragma unroll
        for (int ks = 0; ks < 8; ++ks) {
            #pragma unroll
            for (int ntp = 0; ntp < 4; ntp++) {
                uint32_t v0, v1, v2, v3;
                const uint32_t vo = sV + ((vRow + ks * 16) * 144 + (vCol + ntp * 16) * 2);
                LDSM4T(v0, v1, v2, v3, vo);
                MMAF16(o[ntp*2],     pa[ks], v0, v1);
                MMAF16(o[ntp*2+1],   pa[ks], v2, v3);
            }
        }

        __syncthreads();
        if (jt + 2 <= jtmax) cpKV(jt + 2, st);
    }

    const float inv0 = 1.0f / l0, inv1 = 1.0f / l1;
    const size_t row0 = tokQ + warp * 16 + rloc0;
    const int colb = hoff + 2 * (lane & 3);
    #pragma unroll
    for (int nt = 0; nt < 8; nt++) {
        *(__half2*)(Og + row0 * TB_D + colb + nt * 8) =
            __floats2half2_rn(o[nt][0] * inv0, o[nt][1] * inv0);
        *(__half2*)(Og + (row0 + 8) * TB_D + colb + nt * 8) =
            __floats2half2_rn(o[nt][2] * inv1, o[nt][3] * inv1);
    }
}

// ---------------- launch ----------------
extern "C" void kernel_launch(void* const* d_in, const int* in_sizes, int n_in,
                              void* d_out, int out_size)
{
    const float* x  = (const float*)d_in[0];
    const float* wq = (const float*)d_in[1];
    const float* wk = (const float*)d_in[2];
    const float* wv = (const float*)d_in[3];
    const float* wo = (const float*)d_in[4];
    const float* w1 = (const float*)d_in[5];
    const float* w2 = (const float*)d_in[6];
    const float* g1 = (const float*)d_in[7];
    const float* g2 = (const float*)d_in[8];
    float* out = (float*)d_out;

    float *x2;
    __half *h16, *q16, *k16, *v16, *o16, *h216, *mid16;
    __half *wq16, *wk16, *wv16, *wo16, *w116, *w216;
    cudaGetSymbolAddress((void**)&x2,    g_x2);
    cudaGetSymbolAddress((void**)&h16,   g_h16);
    cudaGetSymbolAddress((void**)&q16,   g_q16);
    cudaGetSymbolAddress((void**)&k16,   g_k16);
    cudaGetSymbolAddress((void**)&v16,   g_v16);
    cudaGetSymbolAddress((void**)&o16,   g_o16);
    cudaGetSymbolAddress((void**)&h216,  g_h216);
    cudaGetSymbolAddress((void**)&mid16, g_mid16);
    cudaGetSymbolAddress((void**)&wq16,  g_wq16);
    cudaGetSymbolAddress((void**)&wk16,  g_wk16);
    cudaGetSymbolAddress((void**)&wv16,  g_wv16);
    cudaGetSymbolAddress((void**)&wo16,  g_wo16);
    cudaGetSymbolAddress((void**)&w116,  g_w116);
    cudaGetSymbolAddress((void**)&w216,  g_w216);

    cudaFuncSetAttribute(gemm_qkv_k,  cudaFuncAttributeMaxDynamicSharedMemorySize, GEMM_SMEM);
    cudaFuncSetAttribute(gemm_res_k,  cudaFuncAttributeMaxDynamicSharedMemorySize, GEMM_SMEM);
    cudaFuncSetAttribute(gemm_gelu_k, cudaFuncAttributeMaxDynamicSharedMemorySize, GEMM_SMEM);
    cudaFuncSetAttribute(attn_kernel, cudaFuncAttributeMaxDynamicSharedMemorySize, AT_SMEM);

    // 1: all weight converts (single launch)
    conv_all_kernel<<<12288, 256>>>(wq, wq16, wk, wk16, wv, wv16, wo, wo16,
                                    w1, w116, w2, w216);
    // 2: h = rmsnorm(x, g1) -> fp16
    rmsnorm_h_kernel<<<TB_M, 256>>>(x, g1, h16);
    // 3: q,k,v (fp16; q pre-scaled by 0.125*log2e)
    gemm_qkv_k<<<dim3(TB_D / 128, TB_M / 128, 3), 256, GEMM_SMEM>>>(
        h16, wq16, wk16, wv16, q16, k16, v16);
    // 4: attention -> o fp16 (Bc=128, f16x2 exp)
    attn_kernel<<<dim3(TB_S / 128, TB_H, TB_B), 256, AT_SMEM>>>(q16, k16, v16, o16);
    // 5: x2 = o @ wo^T + x
    gemm_res_k<<<dim3(TB_D / 128, TB_M / 128), 256, GEMM_SMEM>>>(
        o16, wo16, x, x2, TB_D, TB_D);
    // 6: h2 = rmsnorm(x2, g2) -> fp16
    rmsnorm_h_kernel<<<TB_M, 256>>>(x2, g2, h216);
    // 7: mid = gelu(h2 @ w1^T) -> fp16
    gemm_gelu_k<<<dim3(TB_FF / 128, TB_M / 128), 256, GEMM_SMEM>>>(
        h216, w116, mid16, TB_FF, TB_D);
    // 8: out = mid @ w2^T + x2
    gemm_res_k<<<dim3(TB_D / 128, TB_M / 128), 256, GEMM_SMEM>>>(
        mid16, w216, x2, out, TB_D, TB_FF);
}